// round 1
// baseline (speedup 1.0000x reference)
#include <cuda_runtime.h>

// ---------------- problem constants (fixed shapes from reference) ------------
#define NSRC0 256000
#define NDST0 25600
#define NDST1 5120
#define NDST2 1024
#define NE0   256000
#define NE1   51200
#define NE2   10240
#define DIN   128
#define DH    256
#define DOUT  64

// ---------------- device scratch (no allocations allowed) --------------------
__device__ float g_acc[NDST0 * DIN];   // 3.28M floats; also covers 5120*256 and 1024*256
__device__ int   g_cnt[NDST0];
__device__ float g_h1[NDST0 * DH];     // layer-0 output (25600 x 256)
__device__ float g_h2[NDST1 * DH];     // layer-1 output (5120 x 256)
__device__ float g_stats[2 * DH];      // per-column sum, sumsq
__device__ float g_ab[2 * DH];         // per-column BN scale a, shift b

// ---------------- edge scatter: acc[dst] += x[src], cnt[dst]++ ---------------
// one warp per edge; row is contiguous (D floats), loaded as float4
template <int D>
__global__ void k_scatter(const float* __restrict__ x, const int* __restrict__ src,
                          const int* __restrict__ dst, float* __restrict__ acc,
                          int* __restrict__ cnt, int nE) {
    int w    = (blockIdx.x * blockDim.x + threadIdx.x) >> 5;
    int lane = threadIdx.x & 31;
    if (w >= nE) return;
    int s = src[w], d = dst[w];
    const float4* xs = (const float4*)(x + (long)s * D);
    float* ad = acc + (long)d * D;
    if (lane == 0) atomicAdd(&cnt[d], 1);
#pragma unroll
    for (int k = lane; k < D / 4; k += 32) {
        float4 v = xs[k];
        atomicAdd(ad + 4 * k + 0, v.x);
        atomicAdd(ad + 4 * k + 1, v.y);
        atomicAdd(ad + 4 * k + 2, v.z);
        atomicAdd(ad + 4 * k + 3, v.w);
    }
}

// ---------------- mean finalize: acc[r,:] /= max(cnt[r],1) -------------------
__global__ void k_div(float* __restrict__ acc, const int* __restrict__ cnt, int M, int D) {
    int i  = blockIdx.x * blockDim.x + threadIdx.x;
    int n4 = M * D / 4;
    if (i >= n4) return;
    int r   = i / (D / 4);
    int c   = cnt[r];
    float f = (float)(c > 0 ? c : 1);
    float4 v = ((float4*)acc)[i];
    v.x /= f; v.y /= f; v.z /= f; v.w /= f;
    ((float4*)acc)[i] = v;
}

// ---------------- fused dual GEMM: C = A1@B1 + bias + A2@B2 ------------------
// A1, A2: M x K0 row-major (row stride == K0). B1, B2: K0 x N row-major.
// 64x64 block tile, 4x4 per thread, BK=16. Requires M%64==0, N%64==0, K0%16==0.
// Optional epilogue accumulates per-column sum/sumsq into stats[0..N) / stats[N..2N).
__global__ void k_gemm(const float* __restrict__ A1, const float* __restrict__ A2,
                       const float* __restrict__ B1, const float* __restrict__ B2,
                       const float* __restrict__ bias, float* __restrict__ C,
                       int M, int K0, int N, float* __restrict__ stats) {
    __shared__ float As[16][68];
    __shared__ float Bs[16][68];
    const int tid = threadIdx.x;
    const int tx = tid & 15, ty = tid >> 4;
    const int m0 = blockIdx.x * 64, n0 = blockIdx.y * 64;
    const int lr = tid >> 2;          // A-load row within tile (0..63)
    const int lk = (tid & 3) * 4;     // A-load k within tile (0,4,8,12)
    const int bk = tid >> 4;          // B-load k within tile (0..15)
    const int bn = (tid & 15) * 4;    // B-load col within tile

    float acc[4][4] = {};
    const int K2 = 2 * K0;
    for (int kb = 0; kb < K2; kb += 16) {
        const float* A = (kb < K0) ? A1 : A2;
        const float* B = (kb < K0) ? B1 : B2;
        const int ko   = (kb < K0) ? kb : kb - K0;

        float4 av = *(const float4*)(A + (long)(m0 + lr) * K0 + ko + lk);
        As[lk + 0][lr] = av.x;
        As[lk + 1][lr] = av.y;
        As[lk + 2][lr] = av.z;
        As[lk + 3][lr] = av.w;
        *(float4*)&Bs[bk][bn] = *(const float4*)(B + (long)(ko + bk) * N + n0 + bn);
        __syncthreads();

#pragma unroll
        for (int k = 0; k < 16; k++) {
            float a[4], b[4];
#pragma unroll
            for (int i = 0; i < 4; i++) a[i] = As[k][ty * 4 + i];
#pragma unroll
            for (int j = 0; j < 4; j++) b[j] = Bs[k][tx * 4 + j];
#pragma unroll
            for (int i = 0; i < 4; i++)
#pragma unroll
                for (int j = 0; j < 4; j++) acc[i][j] += a[i] * b[j];
        }
        __syncthreads();
    }

    float sv[4] = {0.f, 0.f, 0.f, 0.f}, qv[4] = {0.f, 0.f, 0.f, 0.f};
#pragma unroll
    for (int i = 0; i < 4; i++) {
#pragma unroll
        for (int j = 0; j < 4; j++) {
            float v = acc[i][j] + bias[n0 + tx * 4 + j];
            C[(long)(m0 + ty * 4 + i) * N + n0 + tx * 4 + j] = v;
            sv[j] += v;
            qv[j] += v * v;
        }
    }

    if (stats) {  // block-level column reduction, then one atomic per (block, col)
        float* sA = &As[0][0];
        float* sB = &Bs[0][0];
        __syncthreads();
#pragma unroll
        for (int j = 0; j < 4; j++) {
            sA[ty * 64 + tx * 4 + j] = sv[j];
            sB[ty * 64 + tx * 4 + j] = qv[j];
        }
        __syncthreads();
        if (ty == 0) {
#pragma unroll
            for (int j = 0; j < 4; j++) {
                float ss = 0.f, qq = 0.f;
                for (int t = 0; t < 16; t++) {
                    ss += sA[t * 64 + tx * 4 + j];
                    qq += sB[t * 64 + tx * 4 + j];
                }
                atomicAdd(&stats[n0 + tx * 4 + j], ss);
                atomicAdd(&stats[N + n0 + tx * 4 + j], qq);
            }
        }
    }
}

// ---------------- BN parameter derivation: a = g*rsqrt(var+eps), b = beta-mean*a
__global__ void k_bnp(const float* __restrict__ stats, const float* __restrict__ gamma,
                      const float* __restrict__ beta, float* __restrict__ ab, int M, int N) {
    int c = threadIdx.x;
    if (c >= N) return;
    float inv  = 1.0f / (float)M;
    float mean = stats[c] * inv;
    float var  = stats[N + c] * inv - mean * mean;
    float r    = rsqrtf(var + 1e-5f);
    float a    = gamma[c] * r;
    ab[c]      = a;
    ab[N + c]  = beta[c] - mean * a;
}

// ---------------- BN apply + ReLU, in place -----------------------------------
__global__ void k_bnrelu(float* __restrict__ h, const float* __restrict__ ab, int rows, int N) {
    int i  = blockIdx.x * blockDim.x + threadIdx.x;
    int n4 = rows * N / 4;
    if (i >= n4) return;
    int c = (i * 4) % N;
    float4 v = ((float4*)h)[i];
    v.x = fmaxf(v.x * ab[c + 0] + ab[N + c + 0], 0.f);
    v.y = fmaxf(v.y * ab[c + 1] + ab[N + c + 1], 0.f);
    v.z = fmaxf(v.z * ab[c + 2] + ab[N + c + 2], 0.f);
    v.w = fmaxf(v.w * ab[c + 3] + ab[N + c + 3], 0.f);
    ((float4*)h)[i] = v;
}

// ---------------- launch ------------------------------------------------------
extern "C" void kernel_launch(void* const* d_in, const int* in_sizes, int n_in,
                              void* d_out, int out_size) {
    const float* x      = (const float*)d_in[0];
    const float* Wl0    = (const float*)d_in[1];
    const float* bl0    = (const float*)d_in[2];
    const float* Wr0    = (const float*)d_in[3];
    const float* Wl1    = (const float*)d_in[4];
    const float* bl1    = (const float*)d_in[5];
    const float* Wr1    = (const float*)d_in[6];
    const float* Wl2    = (const float*)d_in[7];
    const float* bl2    = (const float*)d_in[8];
    const float* Wr2    = (const float*)d_in[9];
    const float* gamma0 = (const float*)d_in[10];
    const float* beta0  = (const float*)d_in[11];
    const float* gamma1 = (const float*)d_in[12];
    const float* beta1  = (const float*)d_in[13];
    const int* src0 = (const int*)d_in[14];
    const int* dst0 = (const int*)d_in[15];
    const int* src1 = (const int*)d_in[16];
    const int* dst1 = (const int*)d_in[17];
    const int* src2 = (const int*)d_in[18];
    const int* dst2 = (const int*)d_in[19];
    float* out = (float*)d_out;

    float *acc, *h1, *h2, *stats, *ab;
    int* cnt;
    cudaGetSymbolAddress((void**)&acc, g_acc);
    cudaGetSymbolAddress((void**)&cnt, g_cnt);
    cudaGetSymbolAddress((void**)&h1, g_h1);
    cudaGetSymbolAddress((void**)&h2, g_h2);
    cudaGetSymbolAddress((void**)&stats, g_stats);
    cudaGetSymbolAddress((void**)&ab, g_ab);

    // ======== layer 0: IN=128 -> H=256, M = 25600 ========
    cudaMemsetAsync(acc, 0, sizeof(float) * NDST0 * DIN, 0);
    cudaMemsetAsync(cnt, 0, sizeof(int) * NDST0, 0);
    cudaMemsetAsync(stats, 0, sizeof(float) * 2 * DH, 0);
    k_scatter<DIN><<<(NE0 + 7) / 8, 256>>>(x, src0, dst0, acc, cnt, NE0);
    {
        int n4 = NDST0 * DIN / 4;
        k_div<<<(n4 + 255) / 256, 256>>>(acc, cnt, NDST0, DIN);
    }
    {
        dim3 g(NDST0 / 64, DH / 64);
        k_gemm<<<g, 256>>>(acc, x, Wl0, Wr0, bl0, h1, NDST0, DIN, DH, stats);
    }
    k_bnp<<<1, DH>>>(stats, gamma0, beta0, ab, NDST0, DH);
    {
        int n4 = NDST0 * DH / 4;
        k_bnrelu<<<(n4 + 255) / 256, 256>>>(h1, ab, NDST0, DH);
    }

    // ======== layer 1: H=256 -> H=256, M = 5120 ========
    cudaMemsetAsync(acc, 0, sizeof(float) * NDST1 * DH, 0);
    cudaMemsetAsync(cnt, 0, sizeof(int) * NDST1, 0);
    cudaMemsetAsync(stats, 0, sizeof(float) * 2 * DH, 0);
    k_scatter<DH><<<(NE1 + 7) / 8, 256>>>(h1, src1, dst1, acc, cnt, NE1);
    {
        int n4 = NDST1 * DH / 4;
        k_div<<<(n4 + 255) / 256, 256>>>(acc, cnt, NDST1, DH);
    }
    {
        dim3 g(NDST1 / 64, DH / 64);
        k_gemm<<<g, 256>>>(acc, h1, Wl1, Wr1, bl1, h2, NDST1, DH, DH, stats);
    }
    k_bnp<<<1, DH>>>(stats, gamma1, beta1, ab, NDST1, DH);
    {
        int n4 = NDST1 * DH / 4;
        k_bnrelu<<<(n4 + 255) / 256, 256>>>(h2, ab, NDST1, DH);
    }

    // ======== layer 2: H=256 -> OUT=64, M = 1024 ========
    cudaMemsetAsync(acc, 0, sizeof(float) * NDST2 * DH, 0);
    cudaMemsetAsync(cnt, 0, sizeof(int) * NDST2, 0);
    k_scatter<DH><<<(NE2 + 7) / 8, 256>>>(h2, src2, dst2, acc, cnt, NE2);
    {
        int n4 = NDST2 * DH / 4;
        k_div<<<(n4 + 255) / 256, 256>>>(acc, cnt, NDST2, DH);
    }
    {
        dim3 g(NDST2 / 64, DOUT / 64);
        k_gemm<<<g, 256>>>(acc, h2, Wl2, Wr2, bl2, out, NDST2, DH, DOUT, nullptr);
    }
}

// round 2
// speedup vs baseline: 1.0365x; 1.0365x over previous
#include <cuda_runtime.h>

// ---------------- problem constants ------------------------------------------
#define NDST0 25600
#define NDST1 5120
#define NDST2 1024
#define NE0   256000
#define NE1   51200
#define NE2   10240
#define DIN   128
#define DH    256
#define DOUT  64

// ---------------- device scratch (no allocations allowed) --------------------
__device__ float g_agg[NDST0 * DIN];     // aggregated means (covers all layers)
__device__ float g_h1[NDST0 * DH];
__device__ float g_h2[NDST1 * DH];
__device__ float g_stats[2 * DH];
__device__ int   g_deg[NDST0];
__device__ int   g_off[NDST0 + 1];
__device__ int   g_cur[NDST0];
__device__ int   g_esrc[NE0];

// ---------------- CSR build ---------------------------------------------------
__global__ void k_hist(const int* __restrict__ dst, int* __restrict__ deg, int nE) {
    int e = blockIdx.x * blockDim.x + threadIdx.x;
    if (e < nE) atomicAdd(&deg[dst[e]], 1);
}

__global__ void k_scan(const int* __restrict__ deg, int* __restrict__ off, int n) {
    __shared__ int part[1024];
    int t = threadIdx.x;
    int chunk = (n + 1023) >> 10;
    int lo = t * chunk, hi = min(lo + chunk, n);
    int s = 0;
    for (int i = lo; i < hi; i++) s += deg[i];
    part[t] = s;
    __syncthreads();
    for (int d = 1; d < 1024; d <<= 1) {
        int v = (t >= d) ? part[t - d] : 0;
        __syncthreads();
        part[t] += v;
        __syncthreads();
    }
    int base = t ? part[t - 1] : 0;
    for (int i = lo; i < hi; i++) { off[i] = base; base += deg[i]; }
    if (t == 1023) off[n] = part[1023];
}

__global__ void k_bucket(const int* __restrict__ src, const int* __restrict__ dst,
                         const int* __restrict__ off, int* __restrict__ cur,
                         int* __restrict__ esrc, int nE) {
    int e = blockIdx.x * blockDim.x + threadIdx.x;
    if (e >= nE) return;
    int d = dst[e];
    int pos = off[d] + atomicAdd(&cur[d], 1);
    esrc[pos] = src[e];
}

// ---------------- gather mean: agg[d] = mean(x[neighbors(d)]) ----------------
// one warp per dst row; D/128 float4 accumulators per lane
template <int D>
__global__ void k_gather(const float* __restrict__ x, const int* __restrict__ esrc,
                         const int* __restrict__ off, float* __restrict__ agg, int nDst) {
    int w    = (blockIdx.x * blockDim.x + threadIdx.x) >> 5;
    int lane = threadIdx.x & 31;
    if (w >= nDst) return;
    int beg = off[w], end = off[w + 1];
    constexpr int R = D / 128;
    float4 acc[R];
#pragma unroll
    for (int r = 0; r < R; r++) acc[r] = make_float4(0.f, 0.f, 0.f, 0.f);

    int e = beg;
    for (; e + 1 < end; e += 2) {  // 2-edge unroll for MLP
        const float4* p0 = (const float4*)(x + (long)esrc[e] * D) + lane;
        const float4* p1 = (const float4*)(x + (long)esrc[e + 1] * D) + lane;
        float4 v0[R], v1[R];
#pragma unroll
        for (int r = 0; r < R; r++) { v0[r] = p0[r * 32]; v1[r] = p1[r * 32]; }
#pragma unroll
        for (int r = 0; r < R; r++) {
            acc[r].x += v0[r].x + v1[r].x;
            acc[r].y += v0[r].y + v1[r].y;
            acc[r].z += v0[r].z + v1[r].z;
            acc[r].w += v0[r].w + v1[r].w;
        }
    }
    if (e < end) {
        const float4* p0 = (const float4*)(x + (long)esrc[e] * D) + lane;
#pragma unroll
        for (int r = 0; r < R; r++) {
            float4 v = p0[r * 32];
            acc[r].x += v.x; acc[r].y += v.y; acc[r].z += v.z; acc[r].w += v.w;
        }
    }
    int c = end - beg;
    float inv = 1.0f / (float)(c > 0 ? c : 1);
    float4* o = (float4*)(agg + (long)w * D) + lane;
#pragma unroll
    for (int r = 0; r < R; r++) {
        acc[r].x *= inv; acc[r].y *= inv; acc[r].z *= inv; acc[r].w *= inv;
        o[r * 32] = acc[r];
    }
}

// ---------------- fused dual GEMM 128x128: C = A1@B1 + bias + A2@B2 ----------
// A1, A2: M x K0 row-major. B1, B2: K0 x N row-major. M%128==0, N%128==0, K0%8==0.
// Optional epilogue: per-column sum/sumsq into stats[0..N)/stats[N..2N).
__global__ __launch_bounds__(256, 2)
void k_gemm128(const float* __restrict__ A1, const float* __restrict__ A2,
               const float* __restrict__ B1, const float* __restrict__ B2,
               const float* __restrict__ bias, float* __restrict__ C,
               int M, int K0, int N, float* __restrict__ stats) {
    __shared__ float As[8][132];
    __shared__ float Bs[8][128];
    __shared__ float sred[2048];

    const int tid = threadIdx.x;
    const int tx = tid & 15, ty = tid >> 4;           // 16x16 thread grid, 8x8 each
    const int m0 = blockIdx.x * 128, n0 = blockIdx.y * 128;
    const int ar = tid >> 1;                           // A-load row (0..127)
    const int ak = (tid & 1) * 4;                      // A-load k (0 or 4)
    const int bk = tid >> 5;                           // B-load k (0..7)
    const int bn = (tid & 31) * 4;                     // B-load col

    float acc[8][8];
#pragma unroll
    for (int i = 0; i < 8; i++)
#pragma unroll
        for (int j = 0; j < 8; j++) acc[i][j] = 0.f;

    const int K2 = 2 * K0;
    for (int kb = 0; kb < K2; kb += 8) {
        const float* A = (kb < K0) ? A1 : A2;
        const float* B = (kb < K0) ? B1 : B2;
        const int ko   = (kb < K0) ? kb : kb - K0;

        float4 av = *(const float4*)(A + (long)(m0 + ar) * K0 + ko + ak);
        As[ak + 0][ar] = av.x;
        As[ak + 1][ar] = av.y;
        As[ak + 2][ar] = av.z;
        As[ak + 3][ar] = av.w;
        *(float4*)&Bs[bk][bn] = *(const float4*)(B + (long)(ko + bk) * N + n0 + bn);
        __syncthreads();

#pragma unroll
        for (int k = 0; k < 8; k++) {
            float4 a0 = *(const float4*)&As[k][ty * 8];
            float4 a1 = *(const float4*)&As[k][ty * 8 + 4];
            float4 b0 = *(const float4*)&Bs[k][tx * 8];
            float4 b1 = *(const float4*)&Bs[k][tx * 8 + 4];
            float a[8] = {a0.x, a0.y, a0.z, a0.w, a1.x, a1.y, a1.z, a1.w};
            float b[8] = {b0.x, b0.y, b0.z, b0.w, b1.x, b1.y, b1.z, b1.w};
#pragma unroll
            for (int i = 0; i < 8; i++)
#pragma unroll
                for (int j = 0; j < 8; j++) acc[i][j] += a[i] * b[j];
        }
        __syncthreads();
    }

    float bb[8];
#pragma unroll
    for (int j = 0; j < 8; j++) bb[j] = bias[n0 + tx * 8 + j];

    float sv[8] = {}, qv[8] = {};
#pragma unroll
    for (int i = 0; i < 8; i++) {
        float* crow = C + (long)(m0 + ty * 8 + i) * N + n0 + tx * 8;
        float4 o0, o1;
        float v0 = acc[i][0] + bb[0], v1 = acc[i][1] + bb[1];
        float v2 = acc[i][2] + bb[2], v3 = acc[i][3] + bb[3];
        float v4 = acc[i][4] + bb[4], v5 = acc[i][5] + bb[5];
        float v6 = acc[i][6] + bb[6], v7 = acc[i][7] + bb[7];
        o0 = make_float4(v0, v1, v2, v3);
        o1 = make_float4(v4, v5, v6, v7);
        *(float4*)crow = o0;
        *(float4*)(crow + 4) = o1;
        sv[0] += v0; sv[1] += v1; sv[2] += v2; sv[3] += v3;
        sv[4] += v4; sv[5] += v5; sv[6] += v6; sv[7] += v7;
        qv[0] += v0 * v0; qv[1] += v1 * v1; qv[2] += v2 * v2; qv[3] += v3 * v3;
        qv[4] += v4 * v4; qv[5] += v5 * v5; qv[6] += v6 * v6; qv[7] += v7 * v7;
    }

    if (stats) {
        // pass 1: column sums
        __syncthreads();
#pragma unroll
        for (int j = 0; j < 8; j++) sred[ty * 128 + tx * 8 + j] = sv[j];
        __syncthreads();
        if (tid < 128) {
            float ss = 0.f;
            for (int t = 0; t < 16; t++) ss += sred[t * 128 + tid];
            atomicAdd(&stats[n0 + tid], ss);
        }
        // pass 2: column sum of squares
        __syncthreads();
#pragma unroll
        for (int j = 0; j < 8; j++) sred[ty * 128 + tx * 8 + j] = qv[j];
        __syncthreads();
        if (tid < 128) {
            float qq = 0.f;
            for (int t = 0; t < 16; t++) qq += sred[t * 128 + tid];
            atomicAdd(&stats[N + n0 + tid], qq);
        }
    }
}

// ---------------- 64x64 dual GEMM for the small final layer -------------------
__global__ void k_gemm64(const float* __restrict__ A1, const float* __restrict__ A2,
                         const float* __restrict__ B1, const float* __restrict__ B2,
                         const float* __restrict__ bias, float* __restrict__ C,
                         int M, int K0, int N) {
    __shared__ float As[16][68];
    __shared__ float Bs[16][68];
    const int tid = threadIdx.x;
    const int tx = tid & 15, ty = tid >> 4;
    const int m0 = blockIdx.x * 64, n0 = blockIdx.y * 64;
    const int lr = tid >> 2;
    const int lk = (tid & 3) * 4;
    const int bk = tid >> 4;
    const int bn = (tid & 15) * 4;

    float acc[4][4] = {};
    const int K2 = 2 * K0;
    for (int kb = 0; kb < K2; kb += 16) {
        const float* A = (kb < K0) ? A1 : A2;
        const float* B = (kb < K0) ? B1 : B2;
        const int ko   = (kb < K0) ? kb : kb - K0;

        float4 av = *(const float4*)(A + (long)(m0 + lr) * K0 + ko + lk);
        As[lk + 0][lr] = av.x;
        As[lk + 1][lr] = av.y;
        As[lk + 2][lr] = av.z;
        As[lk + 3][lr] = av.w;
        *(float4*)&Bs[bk][bn] = *(const float4*)(B + (long)(ko + bk) * N + n0 + bn);
        __syncthreads();

#pragma unroll
        for (int k = 0; k < 16; k++) {
            float a[4], b[4];
#pragma unroll
            for (int i = 0; i < 4; i++) a[i] = As[k][ty * 4 + i];
#pragma unroll
            for (int j = 0; j < 4; j++) b[j] = Bs[k][tx * 4 + j];
#pragma unroll
            for (int i = 0; i < 4; i++)
#pragma unroll
                for (int j = 0; j < 4; j++) acc[i][j] += a[i] * b[j];
        }
        __syncthreads();
    }

#pragma unroll
    for (int i = 0; i < 4; i++)
#pragma unroll
        for (int j = 0; j < 4; j++)
            C[(long)(m0 + ty * 4 + i) * N + n0 + tx * 4 + j] =
                acc[i][j] + bias[n0 + tx * 4 + j];
}

// ---------------- fused BN-param + BN-apply + ReLU (in place) -----------------
__global__ void k_bnrelu(float* __restrict__ h, const float* __restrict__ stats,
                         const float* __restrict__ gamma, const float* __restrict__ beta,
                         int rows, float invM) {
    __shared__ float aa[DH], bb[DH];
    int t = threadIdx.x;
    if (t < DH) {
        float m = stats[t] * invM;
        float v = stats[DH + t] * invM - m * m;
        float a = gamma[t] * rsqrtf(v + 1e-5f);
        aa[t] = a;
        bb[t] = beta[t] - m * a;
    }
    __syncthreads();
    int n4 = rows * DH / 4;
    for (int i = blockIdx.x * blockDim.x + threadIdx.x; i < n4; i += gridDim.x * blockDim.x) {
        int c = (i * 4) & (DH - 1);
        float4 v = ((float4*)h)[i];
        v.x = fmaxf(v.x * aa[c + 0] + bb[c + 0], 0.f);
        v.y = fmaxf(v.y * aa[c + 1] + bb[c + 1], 0.f);
        v.z = fmaxf(v.z * aa[c + 2] + bb[c + 2], 0.f);
        v.w = fmaxf(v.w * aa[c + 3] + bb[c + 3], 0.f);
        ((float4*)h)[i] = v;
    }
}

// ---------------- launch ------------------------------------------------------
static void run_layer_csr(const int* src, const int* dst, int nE, int nDst,
                          int* deg, int* off, int* cur, int* esrc) {
    cudaMemsetAsync(deg, 0, sizeof(int) * nDst, 0);
    cudaMemsetAsync(cur, 0, sizeof(int) * nDst, 0);
    k_hist<<<(nE + 255) / 256, 256>>>(dst, deg, nE);
    k_scan<<<1, 1024>>>(deg, off, nDst);
    k_bucket<<<(nE + 255) / 256, 256>>>(src, dst, off, cur, esrc, nE);
}

extern "C" void kernel_launch(void* const* d_in, const int* in_sizes, int n_in,
                              void* d_out, int out_size) {
    const float* x      = (const float*)d_in[0];
    const float* Wl0    = (const float*)d_in[1];
    const float* bl0    = (const float*)d_in[2];
    const float* Wr0    = (const float*)d_in[3];
    const float* Wl1    = (const float*)d_in[4];
    const float* bl1    = (const float*)d_in[5];
    const float* Wr1    = (const float*)d_in[6];
    const float* Wl2    = (const float*)d_in[7];
    const float* bl2    = (const float*)d_in[8];
    const float* Wr2    = (const float*)d_in[9];
    const float* gamma0 = (const float*)d_in[10];
    const float* beta0  = (const float*)d_in[11];
    const float* gamma1 = (const float*)d_in[12];
    const float* beta1  = (const float*)d_in[13];
    const int* src0 = (const int*)d_in[14];
    const int* dst0 = (const int*)d_in[15];
    const int* src1 = (const int*)d_in[16];
    const int* dst1 = (const int*)d_in[17];
    const int* src2 = (const int*)d_in[18];
    const int* dst2 = (const int*)d_in[19];
    float* out = (float*)d_out;

    float *agg, *h1, *h2, *stats;
    int *deg, *off, *cur, *esrc;
    cudaGetSymbolAddress((void**)&agg, g_agg);
    cudaGetSymbolAddress((void**)&h1, g_h1);
    cudaGetSymbolAddress((void**)&h2, g_h2);
    cudaGetSymbolAddress((void**)&stats, g_stats);
    cudaGetSymbolAddress((void**)&deg, g_deg);
    cudaGetSymbolAddress((void**)&off, g_off);
    cudaGetSymbolAddress((void**)&cur, g_cur);
    cudaGetSymbolAddress((void**)&esrc, g_esrc);

    // ======== layer 0: IN=128 -> H=256, M = 25600 ========
    cudaMemsetAsync(stats, 0, sizeof(float) * 2 * DH, 0);
    run_layer_csr(src0, dst0, NE0, NDST0, deg, off, cur, esrc);
    k_gather<DIN><<<(NDST0 * 32 + 255) / 256, 256>>>(x, esrc, off, agg, NDST0);
    {
        dim3 g(NDST0 / 128, DH / 128);
        k_gemm128<<<g, 256>>>(agg, x, Wl0, Wr0, bl0, h1, NDST0, DIN, DH, stats);
    }
    k_bnrelu<<<1024, 256>>>(h1, stats, gamma0, beta0, NDST0, 1.0f / NDST0);

    // ======== layer 1: H=256 -> H=256, M = 5120 ========
    cudaMemsetAsync(stats, 0, sizeof(float) * 2 * DH, 0);
    run_layer_csr(src1, dst1, NE1, NDST1, deg, off, cur, esrc);
    k_gather<DH><<<(NDST1 * 32 + 255) / 256, 256>>>(h1, esrc, off, agg, NDST1);
    {
        dim3 g(NDST1 / 128, DH / 128);
        k_gemm128<<<g, 256>>>(agg, h1, Wl1, Wr1, bl1, h2, NDST1, DH, DH, stats);
    }
    k_bnrelu<<<512, 256>>>(h2, stats, gamma1, beta1, NDST1, 1.0f / NDST1);

    // ======== layer 2: H=256 -> OUT=64, M = 1024 ========
    run_layer_csr(src2, dst2, NE2, NDST2, deg, off, cur, esrc);
    k_gather<DH><<<(NDST2 * 32 + 255) / 256, 256>>>(h2, esrc, off, agg, NDST2);
    {
        dim3 g(NDST2 / 64, DOUT / 64);
        k_gemm64<<<g, 256>>>(agg, h2, Wl2, Wr2, bl2, out, NDST2, DH, DOUT);
    }
}

// round 4
// speedup vs baseline: 1.3937x; 1.3446x over previous
#include <cuda_runtime.h>

// ---------------- problem constants ------------------------------------------
#define NDST0 25600
#define NDST1 5120
#define NDST2 1024
#define NE0   256000
#define NE1   51200
#define NE2   10240
#define DIN   128
#define DH    256
#define DOUT  64

// ---------------- device scratch (no allocations allowed) --------------------
__device__ float g_agg[NDST0 * DIN];
__device__ float g_h1[NDST0 * DH];
__device__ float g_h2[NDST1 * DH];
__device__ float g_stats[2 * DH];
__device__ int   g_deg[NDST0];
__device__ int   g_off[NDST0 + 1];
__device__ int   g_cur[NDST0];
__device__ int   g_esrc[NE0];

// ---------------- CSR build ---------------------------------------------------
__global__ void k_hist(const int* __restrict__ dst, int* __restrict__ deg, int nE) {
    int e = blockIdx.x * blockDim.x + threadIdx.x;
    if (e < nE) atomicAdd(&deg[dst[e]], 1);
}

__global__ void k_scan(const int* __restrict__ deg, int* __restrict__ off, int n) {
    __shared__ int part[1024];
    int t = threadIdx.x;
    int chunk = (n + 1023) >> 10;
    int lo = t * chunk, hi = min(lo + chunk, n);
    int s = 0;
    for (int i = lo; i < hi; i++) s += deg[i];
    part[t] = s;
    __syncthreads();
    for (int d = 1; d < 1024; d <<= 1) {
        int v = (t >= d) ? part[t - d] : 0;
        __syncthreads();
        part[t] += v;
        __syncthreads();
    }
    int base = t ? part[t - 1] : 0;
    for (int i = lo; i < hi; i++) { off[i] = base; base += deg[i]; }
    if (t == 1023) off[n] = part[1023];
}

__global__ void k_bucket(const int* __restrict__ src, const int* __restrict__ dst,
                         const int* __restrict__ off, int* __restrict__ cur,
                         int* __restrict__ esrc, int nE) {
    int e = blockIdx.x * blockDim.x + threadIdx.x;
    if (e >= nE) return;
    int d = dst[e];
    int pos = off[d] + atomicAdd(&cur[d], 1);
    esrc[pos] = src[e];
}

// ---------------- gather mean -------------------------------------------------
template <int D>
__global__ void k_gather(const float* __restrict__ x, const int* __restrict__ esrc,
                         const int* __restrict__ off, float* __restrict__ agg, int nDst) {
    int w    = (blockIdx.x * blockDim.x + threadIdx.x) >> 5;
    int lane = threadIdx.x & 31;
    if (w >= nDst) return;
    int beg = off[w], end = off[w + 1];
    constexpr int R = D / 128;
    float4 acc[R];
#pragma unroll
    for (int r = 0; r < R; r++) acc[r] = make_float4(0.f, 0.f, 0.f, 0.f);

    int e = beg;
    for (; e + 1 < end; e += 2) {
        const float4* p0 = (const float4*)(x + (long)esrc[e] * D) + lane;
        const float4* p1 = (const float4*)(x + (long)esrc[e + 1] * D) + lane;
        float4 v0[R], v1[R];
#pragma unroll
        for (int r = 0; r < R; r++) { v0[r] = p0[r * 32]; v1[r] = p1[r * 32]; }
#pragma unroll
        for (int r = 0; r < R; r++) {
            acc[r].x += v0[r].x + v1[r].x;
            acc[r].y += v0[r].y + v1[r].y;
            acc[r].z += v0[r].z + v1[r].z;
            acc[r].w += v0[r].w + v1[r].w;
        }
    }
    if (e < end) {
        const float4* p0 = (const float4*)(x + (long)esrc[e] * D) + lane;
#pragma unroll
        for (int r = 0; r < R; r++) {
            float4 v = p0[r * 32];
            acc[r].x += v.x; acc[r].y += v.y; acc[r].z += v.z; acc[r].w += v.w;
        }
    }
    int c = end - beg;
    float inv = 1.0f / (float)(c > 0 ? c : 1);
    float4* o = (float4*)(agg + (long)w * D) + lane;
#pragma unroll
    for (int r = 0; r < R; r++) {
        acc[r].x *= inv; acc[r].y *= inv; acc[r].z *= inv; acc[r].w *= inv;
        o[r * 32] = acc[r];
    }
}

// ---------------- tf32 helpers ------------------------------------------------
__device__ __forceinline__ float tf32r(float x) {
    unsigned u;
    asm("cvt.rna.tf32.f32 %0, %1;" : "=r"(u) : "f"(x));
    return __uint_as_float(u);
}

__device__ __forceinline__ void mma_tf32(float (&d)[4], const unsigned (&a)[4],
                                         const unsigned (&b)[2]) {
    asm volatile(
        "mma.sync.aligned.m16n8k8.row.col.f32.tf32.tf32.f32 "
        "{%0,%1,%2,%3}, {%4,%5,%6,%7}, {%8,%9}, {%0,%1,%2,%3};\n"
        : "+f"(d[0]), "+f"(d[1]), "+f"(d[2]), "+f"(d[3])
        : "r"(a[0]), "r"(a[1]), "r"(a[2]), "r"(a[3]), "r"(b[0]), "r"(b[1]));
}

// ---------------- tensor-core fused dual GEMM --------------------------------
// C = round_tf32(A1)@round_tf32(B1) + bias + round_tf32(A2)@round_tf32(B2)
// Block 128x128, 8 warps (2x4), warp tile 64x32, BK=16.
// M%128==0, N%128==0, K0%16==0. Optional BN-stats epilogue.
#define TCBK 16
__global__ __launch_bounds__(256, 2)
void k_gemm_tc(const float* __restrict__ A1, const float* __restrict__ A2,
               const float* __restrict__ B1, const float* __restrict__ B2,
               const float* __restrict__ bias, float* __restrict__ C,
               int M, int K0, int N, float* __restrict__ stats) {
    __shared__ float As[TCBK][132];
    __shared__ float Bs[TCBK][132];
    __shared__ float s_sum[128];
    __shared__ float s_sq[128];

    const int tid  = threadIdx.x;
    const int lane = tid & 31;
    const int warp = tid >> 5;
    const int mw = (warp & 1) * 64;    // warp m offset
    const int nw = (warp >> 1) * 32;   // warp n offset
    const int m0 = blockIdx.x * 128, n0 = blockIdx.y * 128;
    const int q = lane & 3, r = lane >> 2;

    const int ar = tid >> 1;           // A-load row (0..127)
    const int ak = (tid & 1) * 8;      // A-load k base (0 or 8)
    const int bk = tid >> 4;           // B-load k (0..15)
    const int bn = (tid & 15) * 8;     // B-load col base

    if (tid < 128) { s_sum[tid] = 0.f; s_sq[tid] = 0.f; }

    float acc[4][4][4];
#pragma unroll
    for (int mf = 0; mf < 4; mf++)
#pragma unroll
        for (int nf = 0; nf < 4; nf++)
#pragma unroll
            for (int c = 0; c < 4; c++) acc[mf][nf][c] = 0.f;

    const int K2 = 2 * K0;
    for (int kb = 0; kb < K2; kb += TCBK) {
        const float* A = (kb < K0) ? A1 : A2;
        const float* B = (kb < K0) ? B1 : B2;
        const int ko   = (kb < K0) ? kb : kb - K0;

        // A tile -> As[k][m] (k-major), tf32-rounded
        {
            const float* ap = A + (long)(m0 + ar) * K0 + ko + ak;
            float4 v0 = *(const float4*)ap;
            float4 v1 = *(const float4*)(ap + 4);
            As[ak + 0][ar] = tf32r(v0.x);
            As[ak + 1][ar] = tf32r(v0.y);
            As[ak + 2][ar] = tf32r(v0.z);
            As[ak + 3][ar] = tf32r(v0.w);
            As[ak + 4][ar] = tf32r(v1.x);
            As[ak + 5][ar] = tf32r(v1.y);
            As[ak + 6][ar] = tf32r(v1.z);
            As[ak + 7][ar] = tf32r(v1.w);
        }
        // B tile -> Bs[k][n], tf32-rounded
        {
            const float* bp = B + (long)(ko + bk) * N + n0 + bn;
            float4 w0 = *(const float4*)bp;
            float4 w1 = *(const float4*)(bp + 4);
            Bs[bk][bn + 0] = tf32r(w0.x);
            Bs[bk][bn + 1] = tf32r(w0.y);
            Bs[bk][bn + 2] = tf32r(w0.z);
            Bs[bk][bn + 3] = tf32r(w0.w);
            Bs[bk][bn + 4] = tf32r(w1.x);
            Bs[bk][bn + 5] = tf32r(w1.y);
            Bs[bk][bn + 6] = tf32r(w1.z);
            Bs[bk][bn + 7] = tf32r(w1.w);
        }
        __syncthreads();

#pragma unroll
        for (int ks = 0; ks < TCBK; ks += 8) {
            unsigned a[4][4], b[4][2];
#pragma unroll
            for (int mf = 0; mf < 4; mf++) {
                int m = mw + mf * 16 + r;
                a[mf][0] = __float_as_uint(As[ks + q][m]);
                a[mf][1] = __float_as_uint(As[ks + q][m + 8]);
                a[mf][2] = __float_as_uint(As[ks + q + 4][m]);
                a[mf][3] = __float_as_uint(As[ks + q + 4][m + 8]);
            }
#pragma unroll
            for (int nf = 0; nf < 4; nf++) {
                int n = nw + nf * 8 + r;
                b[nf][0] = __float_as_uint(Bs[ks + q][n]);
                b[nf][1] = __float_as_uint(Bs[ks + q + 4][n]);
            }
#pragma unroll
            for (int mf = 0; mf < 4; mf++)
#pragma unroll
                for (int nf = 0; nf < 4; nf++)
                    mma_tf32(acc[mf][nf], a[mf], b[nf]);
        }
        __syncthreads();
    }

    // bias per (nf, even/odd col)
    float bs0[4], bs1[4];
#pragma unroll
    for (int nf = 0; nf < 4; nf++) {
        int c = n0 + nw + nf * 8 + 2 * q;
        bs0[nf] = bias[c];
        bs1[nf] = bias[c + 1];
    }

    float csum0[4] = {}, csum1[4] = {}, csq0[4] = {}, csq1[4] = {};
#pragma unroll
    for (int mf = 0; mf < 4; mf++) {
        int row0 = m0 + mw + mf * 16 + r;
#pragma unroll
        for (int nf = 0; nf < 4; nf++) {
            int col = n0 + nw + nf * 8 + 2 * q;
            float v0 = acc[mf][nf][0] + bs0[nf];
            float v1 = acc[mf][nf][1] + bs1[nf];
            float v2 = acc[mf][nf][2] + bs0[nf];
            float v3 = acc[mf][nf][3] + bs1[nf];
            *(float2*)(C + (long)row0 * N + col)       = make_float2(v0, v1);
            *(float2*)(C + (long)(row0 + 8) * N + col) = make_float2(v2, v3);
            csum0[nf] += v0 + v2;
            csum1[nf] += v1 + v3;
            csq0[nf]  += v0 * v0 + v2 * v2;
            csq1[nf]  += v1 * v1 + v3 * v3;
        }
    }

    if (stats) {
#pragma unroll
        for (int nf = 0; nf < 4; nf++) {
            int cl = nw + nf * 8 + 2 * q;
            atomicAdd(&s_sum[cl],     csum0[nf]);
            atomicAdd(&s_sum[cl + 1], csum1[nf]);
            atomicAdd(&s_sq[cl],      csq0[nf]);
            atomicAdd(&s_sq[cl + 1],  csq1[nf]);
        }
        __syncthreads();
        if (tid < 128) {
            atomicAdd(&stats[n0 + tid],     s_sum[tid]);
            atomicAdd(&stats[N + n0 + tid], s_sq[tid]);
        }
    }
}

// ---------------- 64x64 FFMA dual GEMM for the tiny final layer ---------------
__global__ void k_gemm64(const float* __restrict__ A1, const float* __restrict__ A2,
                         const float* __restrict__ B1, const float* __restrict__ B2,
                         const float* __restrict__ bias, float* __restrict__ C,
                         int M, int K0, int N) {
    __shared__ float As[16][68];
    __shared__ float Bs[16][68];
    const int tid = threadIdx.x;
    const int tx = tid & 15, ty = tid >> 4;
    const int m0 = blockIdx.x * 64, n0 = blockIdx.y * 64;
    const int lr = tid >> 2;
    const int lk = (tid & 3) * 4;
    const int bk = tid >> 4;
    const int bn = (tid & 15) * 4;

    float acc[4][4] = {};
    const int K2 = 2 * K0;
    for (int kb = 0; kb < K2; kb += 16) {
        const float* A = (kb < K0) ? A1 : A2;
        const float* B = (kb < K0) ? B1 : B2;
        const int ko   = (kb < K0) ? kb : kb - K0;

        float4 av = *(const float4*)(A + (long)(m0 + lr) * K0 + ko + lk);
        As[lk + 0][lr] = av.x;
        As[lk + 1][lr] = av.y;
        As[lk + 2][lr] = av.z;
        As[lk + 3][lr] = av.w;
        *(float4*)&Bs[bk][bn] = *(const float4*)(B + (long)(ko + bk) * N + n0 + bn);
        __syncthreads();

#pragma unroll
        for (int k = 0; k < 16; k++) {
            float a[4], b[4];
#pragma unroll
            for (int i = 0; i < 4; i++) a[i] = As[k][ty * 4 + i];
#pragma unroll
            for (int j = 0; j < 4; j++) b[j] = Bs[k][tx * 4 + j];
#pragma unroll
            for (int i = 0; i < 4; i++)
#pragma unroll
                for (int j = 0; j < 4; j++) acc[i][j] += a[i] * b[j];
        }
        __syncthreads();
    }

#pragma unroll
    for (int i = 0; i < 4; i++)
#pragma unroll
        for (int j = 0; j < 4; j++)
            C[(long)(m0 + ty * 4 + i) * N + n0 + tx * 4 + j] =
                acc[i][j] + bias[n0 + tx * 4 + j];
}

// ---------------- fused BN-param + BN-apply + ReLU (in place) -----------------
__global__ void k_bnrelu(float* __restrict__ h, const float* __restrict__ stats,
                         const float* __restrict__ gamma, const float* __restrict__ beta,
                         int rows, float invM) {
    __shared__ float aa[DH], bb[DH];
    int t = threadIdx.x;
    if (t < DH) {
        float m = stats[t] * invM;
        float v = stats[DH + t] * invM - m * m;
        float a = gamma[t] * rsqrtf(v + 1e-5f);
        aa[t] = a;
        bb[t] = beta[t] - m * a;
    }
    __syncthreads();
    int n4 = rows * DH / 4;
    for (int i = blockIdx.x * blockDim.x + threadIdx.x; i < n4; i += gridDim.x * blockDim.x) {
        int c = (i * 4) & (DH - 1);
        float4 v = ((float4*)h)[i];
        v.x = fmaxf(v.x * aa[c + 0] + bb[c + 0], 0.f);
        v.y = fmaxf(v.y * aa[c + 1] + bb[c + 1], 0.f);
        v.z = fmaxf(v.z * aa[c + 2] + bb[c + 2], 0.f);
        v.w = fmaxf(v.w * aa[c + 3] + bb[c + 3], 0.f);
        ((float4*)h)[i] = v;
    }
}

// ---------------- launch ------------------------------------------------------
static void run_layer_csr(const int* src, const int* dst, int nE, int nDst,
                          int* deg, int* off, int* cur, int* esrc) {
    cudaMemsetAsync(deg, 0, sizeof(int) * nDst, 0);
    cudaMemsetAsync(cur, 0, sizeof(int) * nDst, 0);
    k_hist<<<(nE + 255) / 256, 256>>>(dst, deg, nE);
    k_scan<<<1, 1024>>>(deg, off, nDst);
    k_bucket<<<(nE + 255) / 256, 256>>>(src, dst, off, cur, esrc, nE);
}

extern "C" void kernel_launch(void* const* d_in, const int* in_sizes, int n_in,
                              void* d_out, int out_size) {
    const float* x      = (const float*)d_in[0];
    const float* Wl0    = (const float*)d_in[1];
    const float* bl0    = (const float*)d_in[2];
    const float* Wr0    = (const float*)d_in[3];
    const float* Wl1    = (const float*)d_in[4];
    const float* bl1    = (const float*)d_in[5];
    const float* Wr1    = (const float*)d_in[6];
    const float* Wl2    = (const float*)d_in[7];
    const float* bl2    = (const float*)d_in[8];
    const float* Wr2    = (const float*)d_in[9];
    const float* gamma0 = (const float*)d_in[10];
    const float* beta0  = (const float*)d_in[11];
    const float* gamma1 = (const float*)d_in[12];
    const float* beta1  = (const float*)d_in[13];
    const int* src0 = (const int*)d_in[14];
    const int* dst0 = (const int*)d_in[15];
    const int* src1 = (const int*)d_in[16];
    const int* dst1 = (const int*)d_in[17];
    const int* src2 = (const int*)d_in[18];
    const int* dst2 = (const int*)d_in[19];
    float* out = (float*)d_out;

    float *agg, *h1, *h2, *stats;
    int *deg, *off, *cur, *esrc;
    cudaGetSymbolAddress((void**)&agg, g_agg);
    cudaGetSymbolAddress((void**)&h1, g_h1);
    cudaGetSymbolAddress((void**)&h2, g_h2);
    cudaGetSymbolAddress((void**)&stats, g_stats);
    cudaGetSymbolAddress((void**)&deg, g_deg);
    cudaGetSymbolAddress((void**)&off, g_off);
    cudaGetSymbolAddress((void**)&cur, g_cur);
    cudaGetSymbolAddress((void**)&esrc, g_esrc);

    // ======== layer 0: IN=128 -> H=256, M = 25600 ========
    cudaMemsetAsync(stats, 0, sizeof(float) * 2 * DH, 0);
    run_layer_csr(src0, dst0, NE0, NDST0, deg, off, cur, esrc);
    k_gather<DIN><<<(NDST0 * 32 + 255) / 256, 256>>>(x, esrc, off, agg, NDST0);
    {
        dim3 g(NDST0 / 128, DH / 128);
        k_gemm_tc<<<g, 256>>>(agg, x, Wl0, Wr0, bl0, h1, NDST0, DIN, DH, stats);
    }
    k_bnrelu<<<1024, 256>>>(h1, stats, gamma0, beta0, NDST0, 1.0f / NDST0);

    // ======== layer 1: H=256 -> H=256, M = 5120 ========
    cudaMemsetAsync(stats, 0, sizeof(float) * 2 * DH, 0);
    run_layer_csr(src1, dst1, NE1, NDST1, deg, off, cur, esrc);
    k_gather<DH><<<(NDST1 * 32 + 255) / 256, 256>>>(h1, esrc, off, agg, NDST1);
    {
        dim3 g(NDST1 / 128, DH / 128);
        k_gemm_tc<<<g, 256>>>(agg, h1, Wl1, Wr1, bl1, h2, NDST1, DH, DH, stats);
    }
    k_bnrelu<<<512, 256>>>(h2, stats, gamma1, beta1, NDST1, 1.0f / NDST1);

    // ======== layer 2: H=256 -> OUT=64, M = 1024 ========
    run_layer_csr(src2, dst2, NE2, NDST2, deg, off, cur, esrc);
    k_gather<DH><<<(NDST2 * 32 + 255) / 256, 256>>>(h2, esrc, off, agg, NDST2);
    {
        dim3 g(NDST2 / 64, DOUT / 64);
        k_gemm64<<<g, 256>>>(agg, h2, Wl2, Wr2, bl2, out, NDST2, DH, DOUT);
    }
}

// round 5
// speedup vs baseline: 1.6456x; 1.1808x over previous
#include <cuda_runtime.h>

// ---------------- problem constants ------------------------------------------
#define NDST0 25600
#define NDST1 5120
#define NDST2 1024
#define NTOT  (NDST0 + NDST1 + NDST2)
#define NE0   256000
#define NE1   51200
#define NE2   10240
#define NETOT (NE0 + NE1 + NE2)
#define DIN   128
#define DH    256
#define DOUT  64

// ---------------- device scratch (no allocations allowed) --------------------
__device__ float g_agg[NDST0 * DIN];      // gather output (reused per layer)
__device__ float g_h1[NDST0 * DH];        // layer-0 raw GEMM output (pre-BN)
__device__ float g_h2[NDST1 * DH];        // layer-1 raw GEMM output (pre-BN)
__device__ float g_stats[4 * DH];         // [0..512) layer0 sum/sq, [512..1024) layer1
__device__ int   g_cnt[2 * NTOT];         // deg (first NTOT) + cur (second NTOT)
__device__ int   g_off0[NDST0 + 1];
__device__ int   g_off1[NDST1 + 1];
__device__ int   g_off2[NDST2 + 1];
__device__ int   g_esrc0[NE0];
__device__ int   g_esrc1[NE1];
__device__ int   g_esrc2[NE2];

// ---------------- combined CSR build -----------------------------------------
__global__ void k_hist_all(const int* __restrict__ d0, const int* __restrict__ d1,
                           const int* __restrict__ d2, int* __restrict__ deg) {
    int e = blockIdx.x * blockDim.x + threadIdx.x;
    if (e < NE0)                 atomicAdd(&deg[d0[e]], 1);
    else if (e < NE0 + NE1)      atomicAdd(&deg[NDST0 + d1[e - NE0]], 1);
    else if (e < NETOT)          atomicAdd(&deg[NDST0 + NDST1 + d2[e - NE0 - NE1]], 1);
}

__global__ void k_scan3(const int* __restrict__ deg, int* __restrict__ off0,
                        int* __restrict__ off1, int* __restrict__ off2) {
    __shared__ int part[1024];
    int b = blockIdx.x, t = threadIdx.x;
    int n    = (b == 0) ? NDST0 : (b == 1) ? NDST1 : NDST2;
    int base = (b == 0) ? 0 : (b == 1) ? NDST0 : NDST0 + NDST1;
    int* off = (b == 0) ? off0 : (b == 1) ? off1 : off2;
    const int* d = deg + base;

    int chunk = (n + 1023) >> 10;
    int lo = t * chunk, hi = min(lo + chunk, n);
    int s = 0;
    for (int i = lo; i < hi; i++) s += d[i];
    part[t] = s;
    __syncthreads();
    for (int st = 1; st < 1024; st <<= 1) {
        int v = (t >= st) ? part[t - st] : 0;
        __syncthreads();
        part[t] += v;
        __syncthreads();
    }
    int run = t ? part[t - 1] : 0;
    for (int i = lo; i < hi; i++) { off[i] = run; run += d[i]; }
    if (t == 1023) off[n] = part[1023];
}

__global__ void k_bucket_all(const int* __restrict__ s0, const int* __restrict__ d0,
                             const int* __restrict__ s1, const int* __restrict__ d1,
                             const int* __restrict__ s2, const int* __restrict__ d2,
                             const int* __restrict__ off0, const int* __restrict__ off1,
                             const int* __restrict__ off2, int* __restrict__ cur,
                             int* __restrict__ e0, int* __restrict__ e1, int* __restrict__ e2) {
    int e = blockIdx.x * blockDim.x + threadIdx.x;
    if (e < NE0) {
        int d = d0[e];
        e0[off0[d] + atomicAdd(&cur[d], 1)] = s0[e];
    } else if (e < NE0 + NE1) {
        int i = e - NE0, d = d1[i];
        e1[off1[d] + atomicAdd(&cur[NDST0 + d], 1)] = s1[i];
    } else if (e < NETOT) {
        int i = e - NE0 - NE1, d = d2[i];
        e2[off2[d] + atomicAdd(&cur[NDST0 + NDST1 + d], 1)] = s2[i];
    }
}

// ---------------- gather mean (optionally fused BN+ReLU on inputs) ------------
// one warp per dst row. BN=true: x is a raw pre-BN buffer with 256 cols; apply
// v = relu(v*a[c]+b[c]) per element before averaging.
template <int D, bool BN>
__global__ void k_gather(const float* __restrict__ x, const int* __restrict__ esrc,
                         const int* __restrict__ off, float* __restrict__ agg, int nDst,
                         const float* __restrict__ stats, const float* __restrict__ gamma,
                         const float* __restrict__ beta, float invM) {
    constexpr int R = D / 128;
    __shared__ float saa[D], sbb[D];
    int lane = threadIdx.x & 31;
    if (BN) {
        int t = threadIdx.x;
        if (t < D) {
            float m = stats[t] * invM;
            float v = stats[t + D] * invM - m * m;
            float a = gamma[t] * rsqrtf(v + 1e-5f);
            saa[t] = a;
            sbb[t] = beta[t] - m * a;
        }
        __syncthreads();
    }
    int w = (blockIdx.x * blockDim.x + threadIdx.x) >> 5;
    if (w >= nDst) return;

    float4 ca[R], cb[R];
    if (BN) {
#pragma unroll
        for (int r = 0; r < R; r++) {
            ca[r] = *(const float4*)&saa[4 * lane + 128 * r];
            cb[r] = *(const float4*)&sbb[4 * lane + 128 * r];
        }
    }

    int beg = off[w], end = off[w + 1];
    float4 acc[R];
#pragma unroll
    for (int r = 0; r < R; r++) acc[r] = make_float4(0.f, 0.f, 0.f, 0.f);

    int e = beg;
    for (; e + 1 < end; e += 2) {
        const float4* p0 = (const float4*)(x + (long)esrc[e] * D) + lane;
        const float4* p1 = (const float4*)(x + (long)esrc[e + 1] * D) + lane;
        float4 v0[R], v1[R];
#pragma unroll
        for (int r = 0; r < R; r++) { v0[r] = p0[r * 32]; v1[r] = p1[r * 32]; }
#pragma unroll
        for (int r = 0; r < R; r++) {
            if (BN) {
                v0[r].x = fmaxf(fmaf(v0[r].x, ca[r].x, cb[r].x), 0.f);
                v0[r].y = fmaxf(fmaf(v0[r].y, ca[r].y, cb[r].y), 0.f);
                v0[r].z = fmaxf(fmaf(v0[r].z, ca[r].z, cb[r].z), 0.f);
                v0[r].w = fmaxf(fmaf(v0[r].w, ca[r].w, cb[r].w), 0.f);
                v1[r].x = fmaxf(fmaf(v1[r].x, ca[r].x, cb[r].x), 0.f);
                v1[r].y = fmaxf(fmaf(v1[r].y, ca[r].y, cb[r].y), 0.f);
                v1[r].z = fmaxf(fmaf(v1[r].z, ca[r].z, cb[r].z), 0.f);
                v1[r].w = fmaxf(fmaf(v1[r].w, ca[r].w, cb[r].w), 0.f);
            }
            acc[r].x += v0[r].x + v1[r].x;
            acc[r].y += v0[r].y + v1[r].y;
            acc[r].z += v0[r].z + v1[r].z;
            acc[r].w += v0[r].w + v1[r].w;
        }
    }
    if (e < end) {
        const float4* p0 = (const float4*)(x + (long)esrc[e] * D) + lane;
#pragma unroll
        for (int r = 0; r < R; r++) {
            float4 v = p0[r * 32];
            if (BN) {
                v.x = fmaxf(fmaf(v.x, ca[r].x, cb[r].x), 0.f);
                v.y = fmaxf(fmaf(v.y, ca[r].y, cb[r].y), 0.f);
                v.z = fmaxf(fmaf(v.z, ca[r].z, cb[r].z), 0.f);
                v.w = fmaxf(fmaf(v.w, ca[r].w, cb[r].w), 0.f);
            }
            acc[r].x += v.x; acc[r].y += v.y; acc[r].z += v.z; acc[r].w += v.w;
        }
    }
    int c = end - beg;
    float inv = 1.0f / (float)(c > 0 ? c : 1);
    float4* o = (float4*)(agg + (long)w * D) + lane;
#pragma unroll
    for (int r = 0; r < R; r++) {
        acc[r].x *= inv; acc[r].y *= inv; acc[r].z *= inv; acc[r].w *= inv;
        o[r * 32] = acc[r];
    }
}

// ---------------- tf32 helpers ------------------------------------------------
__device__ __forceinline__ float tf32r(float x) {
    unsigned u;
    asm("cvt.rna.tf32.f32 %0, %1;" : "=r"(u) : "f"(x));
    return __uint_as_float(u);
}

__device__ __forceinline__ void mma_tf32(float (&d)[4], const unsigned (&a)[4],
                                         const unsigned (&b)[2]) {
    asm volatile(
        "mma.sync.aligned.m16n8k8.row.col.f32.tf32.tf32.f32 "
        "{%0,%1,%2,%3}, {%4,%5,%6,%7}, {%8,%9}, {%0,%1,%2,%3};\n"
        : "+f"(d[0]), "+f"(d[1]), "+f"(d[2]), "+f"(d[3])
        : "r"(a[0]), "r"(a[1]), "r"(a[2]), "r"(a[3]), "r"(b[0]), "r"(b[1]));
}

// ---------------- tensor-core fused dual GEMM (double-buffered) ---------------
// C = tf32(A1)@tf32(B1) + bias + tf32(bnrelu?(A2))@tf32(B2)
// Block 128x128, 8 warps (2x4), warp tile 64x32, BK=16, 2-stage smem pipeline.
// If bnst != null: A2 elements get relu(v*a[c]+b[c]) applied (c = k column, K0=256).
#define TCBK 16
__global__ __launch_bounds__(256, 2)
void k_gemm_tc(const float* __restrict__ A1, const float* __restrict__ A2,
               const float* __restrict__ B1, const float* __restrict__ B2,
               const float* __restrict__ bias, float* __restrict__ C,
               int M, int K0, int N, float* __restrict__ stats,
               const float* __restrict__ bnst, const float* __restrict__ bng,
               const float* __restrict__ bnb, float bnInv) {
    __shared__ float As[2][TCBK][132];
    __shared__ float Bs[2][TCBK][132];
    __shared__ float s_sum[128];
    __shared__ float s_sq[128];
    __shared__ float s_aa[256];
    __shared__ float s_bb[256];

    const int tid  = threadIdx.x;
    const int lane = tid & 31;
    const int warp = tid >> 5;
    const int mw = (warp & 1) * 64;
    const int nw = (warp >> 1) * 32;
    const int m0 = blockIdx.x * 128, n0 = blockIdx.y * 128;
    const int q = lane & 3, r = lane >> 2;

    const int ar = tid >> 1;          // A-load row (0..127)
    const int ak = (tid & 1) * 8;     // A-load k base (0 or 8)
    const int bk = tid >> 4;          // B-load k (0..15)
    const int bc = (tid & 15) * 8;    // B-load col base

    const bool hasBN = (bnst != nullptr);
    if (hasBN && tid < 256) {
        float m = bnst[tid] * bnInv;
        float v = bnst[tid + 256] * bnInv - m * m;
        float a = bng[tid] * rsqrtf(v + 1e-5f);
        s_aa[tid] = a;
        s_bb[tid] = bnb[tid] - m * a;
    }
    if (tid < 128) { s_sum[tid] = 0.f; s_sq[tid] = 0.f; }

    float acc[4][4][4];
#pragma unroll
    for (int mf = 0; mf < 4; mf++)
#pragma unroll
        for (int nf = 0; nf < 4; nf++)
#pragma unroll
            for (int c = 0; c < 4; c++) acc[mf][nf][c] = 0.f;

    const int K2 = 2 * K0;

    auto ldTile = [&](int kb, float4& a0, float4& a1, float4& b0, float4& b1) {
        const float* A = (kb < K0) ? A1 : A2;
        const float* B = (kb < K0) ? B1 : B2;
        int ko = (kb < K0) ? kb : kb - K0;
        const float* ap = A + (long)(m0 + ar) * K0 + ko + ak;
        a0 = *(const float4*)ap;
        a1 = *(const float4*)(ap + 4);
        const float* bp = B + (long)(ko + bk) * N + n0 + bc;
        b0 = *(const float4*)bp;
        b1 = *(const float4*)(bp + 4);
    };

    auto stTile = [&](int kb, int p, float4 a0, float4 a1, float4 b0, float4 b1) {
        int ko = (kb < K0) ? kb : kb - K0;
        float av[8] = {a0.x, a0.y, a0.z, a0.w, a1.x, a1.y, a1.z, a1.w};
        if (hasBN && kb >= K0) {
            int c = ko + ak;
#pragma unroll
            for (int j = 0; j < 8; j++)
                av[j] = fmaxf(fmaf(av[j], s_aa[c + j], s_bb[c + j]), 0.f);
        }
#pragma unroll
        for (int j = 0; j < 8; j++) As[p][ak + j][ar] = tf32r(av[j]);
        float bv[8] = {b0.x, b0.y, b0.z, b0.w, b1.x, b1.y, b1.z, b1.w};
#pragma unroll
        for (int j = 0; j < 8; j++) Bs[p][bk][bc + j] = tf32r(bv[j]);
    };

    // prologue
    float4 pa0, pa1, pb0, pb1;
    ldTile(0, pa0, pa1, pb0, pb1);
    __syncthreads();                 // BN coeffs + s_sum init visible
    stTile(0, 0, pa0, pa1, pb0, pb1);
    __syncthreads();

    int p = 0;
    for (int kb = 0; kb < K2; kb += TCBK) {
        int nx = kb + TCBK;
        float4 na0, na1, nb0, nb1;
        if (nx < K2) ldTile(nx, na0, na1, nb0, nb1);

#pragma unroll
        for (int ks = 0; ks < TCBK; ks += 8) {
            unsigned a[4][4], b[4][2];
#pragma unroll
            for (int mf = 0; mf < 4; mf++) {
                int m = mw + mf * 16 + r;
                a[mf][0] = __float_as_uint(As[p][ks + q][m]);
                a[mf][1] = __float_as_uint(As[p][ks + q][m + 8]);
                a[mf][2] = __float_as_uint(As[p][ks + q + 4][m]);
                a[mf][3] = __float_as_uint(As[p][ks + q + 4][m + 8]);
            }
#pragma unroll
            for (int nf = 0; nf < 4; nf++) {
                int n = nw + nf * 8 + r;
                b[nf][0] = __float_as_uint(Bs[p][ks + q][n]);
                b[nf][1] = __float_as_uint(Bs[p][ks + q + 4][n]);
            }
#pragma unroll
            for (int mf = 0; mf < 4; mf++)
#pragma unroll
                for (int nf = 0; nf < 4; nf++)
                    mma_tf32(acc[mf][nf], a[mf], b[nf]);
        }

        if (nx < K2) stTile(nx, p ^ 1, na0, na1, nb0, nb1);
        __syncthreads();
        p ^= 1;
    }

    float bs0[4], bs1[4];
#pragma unroll
    for (int nf = 0; nf < 4; nf++) {
        int c = n0 + nw + nf * 8 + 2 * q;
        bs0[nf] = bias[c];
        bs1[nf] = bias[c + 1];
    }

    float csum0[4] = {}, csum1[4] = {}, csq0[4] = {}, csq1[4] = {};
#pragma unroll
    for (int mf = 0; mf < 4; mf++) {
        int row0 = m0 + mw + mf * 16 + r;
#pragma unroll
        for (int nf = 0; nf < 4; nf++) {
            int col = n0 + nw + nf * 8 + 2 * q;
            float v0 = acc[mf][nf][0] + bs0[nf];
            float v1 = acc[mf][nf][1] + bs1[nf];
            float v2 = acc[mf][nf][2] + bs0[nf];
            float v3 = acc[mf][nf][3] + bs1[nf];
            *(float2*)(C + (long)row0 * N + col)       = make_float2(v0, v1);
            *(float2*)(C + (long)(row0 + 8) * N + col) = make_float2(v2, v3);
            csum0[nf] += v0 + v2;
            csum1[nf] += v1 + v3;
            csq0[nf]  += v0 * v0 + v2 * v2;
            csq1[nf]  += v1 * v1 + v3 * v3;
        }
    }

    if (stats) {
#pragma unroll
        for (int nf = 0; nf < 4; nf++) {
            int cl = nw + nf * 8 + 2 * q;
            atomicAdd(&s_sum[cl],     csum0[nf]);
            atomicAdd(&s_sum[cl + 1], csum1[nf]);
            atomicAdd(&s_sq[cl],      csq0[nf]);
            atomicAdd(&s_sq[cl + 1],  csq1[nf]);
        }
        __syncthreads();
        if (tid < 128) {
            atomicAdd(&stats[n0 + tid],     s_sum[tid]);
            atomicAdd(&stats[N + n0 + tid], s_sq[tid]);
        }
    }
}

// ---------------- 64x64 FFMA dual GEMM for the final layer (BN on A2) ---------
__global__ void k_gemm64(const float* __restrict__ A1, const float* __restrict__ A2,
                         const float* __restrict__ B1, const float* __restrict__ B2,
                         const float* __restrict__ bias, float* __restrict__ C,
                         int M, int K0, int N,
                         const float* __restrict__ bnst, const float* __restrict__ bng,
                         const float* __restrict__ bnb, float bnInv) {
    __shared__ float As[16][68];
    __shared__ float Bs[16][68];
    __shared__ float s_aa[256];
    __shared__ float s_bb[256];
    const int tid = threadIdx.x;
    const int tx = tid & 15, ty = tid >> 4;
    const int m0 = blockIdx.x * 64, n0 = blockIdx.y * 64;
    const int lr = tid >> 2;
    const int lk = (tid & 3) * 4;
    const int bk = tid >> 4;
    const int bn = (tid & 15) * 4;

    if (tid < 256) {
        float m = bnst[tid] * bnInv;
        float v = bnst[tid + 256] * bnInv - m * m;
        float a = bng[tid] * rsqrtf(v + 1e-5f);
        s_aa[tid] = a;
        s_bb[tid] = bnb[tid] - m * a;
    }
    __syncthreads();

    float acc[4][4] = {};
    const int K2 = 2 * K0;
    for (int kb = 0; kb < K2; kb += 16) {
        const float* A = (kb < K0) ? A1 : A2;
        const float* B = (kb < K0) ? B1 : B2;
        const int ko   = (kb < K0) ? kb : kb - K0;

        float4 av = *(const float4*)(A + (long)(m0 + lr) * K0 + ko + lk);
        if (kb >= K0) {
            int c = ko + lk;
            av.x = fmaxf(fmaf(av.x, s_aa[c + 0], s_bb[c + 0]), 0.f);
            av.y = fmaxf(fmaf(av.y, s_aa[c + 1], s_bb[c + 1]), 0.f);
            av.z = fmaxf(fmaf(av.z, s_aa[c + 2], s_bb[c + 2]), 0.f);
            av.w = fmaxf(fmaf(av.w, s_aa[c + 3], s_bb[c + 3]), 0.f);
        }
        As[lk + 0][lr] = av.x;
        As[lk + 1][lr] = av.y;
        As[lk + 2][lr] = av.z;
        As[lk + 3][lr] = av.w;
        *(float4*)&Bs[bk][bn] = *(const float4*)(B + (long)(ko + bk) * N + n0 + bn);
        __syncthreads();

#pragma unroll
        for (int k = 0; k < 16; k++) {
            float a[4], b[4];
#pragma unroll
            for (int i = 0; i < 4; i++) a[i] = As[k][ty * 4 + i];
#pragma unroll
            for (int j = 0; j < 4; j++) b[j] = Bs[k][tx * 4 + j];
#pragma unroll
            for (int i = 0; i < 4; i++)
#pragma unroll
                for (int j = 0; j < 4; j++) acc[i][j] += a[i] * b[j];
        }
        __syncthreads();
    }

#pragma unroll
    for (int i = 0; i < 4; i++)
#pragma unroll
        for (int j = 0; j < 4; j++)
            C[(long)(m0 + ty * 4 + i) * N + n0 + tx * 4 + j] =
                acc[i][j] + bias[n0 + tx * 4 + j];
}

// ---------------- launch ------------------------------------------------------
extern "C" void kernel_launch(void* const* d_in, const int* in_sizes, int n_in,
                              void* d_out, int out_size) {
    const float* x      = (const float*)d_in[0];
    const float* Wl0    = (const float*)d_in[1];
    const float* bl0    = (const float*)d_in[2];
    const float* Wr0    = (const float*)d_in[3];
    const float* Wl1    = (const float*)d_in[4];
    const float* bl1    = (const float*)d_in[5];
    const float* Wr1    = (const float*)d_in[6];
    const float* Wl2    = (const float*)d_in[7];
    const float* bl2    = (const float*)d_in[8];
    const float* Wr2    = (const float*)d_in[9];
    const float* gamma0 = (const float*)d_in[10];
    const float* beta0  = (const float*)d_in[11];
    const float* gamma1 = (const float*)d_in[12];
    const float* beta1  = (const float*)d_in[13];
    const int* src0 = (const int*)d_in[14];
    const int* dst0 = (const int*)d_in[15];
    const int* src1 = (const int*)d_in[16];
    const int* dst1 = (const int*)d_in[17];
    const int* src2 = (const int*)d_in[18];
    const int* dst2 = (const int*)d_in[19];
    float* out = (float*)d_out;

    float *agg, *h1, *h2, *stats;
    int *cnt, *off0, *off1, *off2, *e0, *e1, *e2;
    cudaGetSymbolAddress((void**)&agg, g_agg);
    cudaGetSymbolAddress((void**)&h1, g_h1);
    cudaGetSymbolAddress((void**)&h2, g_h2);
    cudaGetSymbolAddress((void**)&stats, g_stats);
    cudaGetSymbolAddress((void**)&cnt, g_cnt);
    cudaGetSymbolAddress((void**)&off0, g_off0);
    cudaGetSymbolAddress((void**)&off1, g_off1);
    cudaGetSymbolAddress((void**)&off2, g_off2);
    cudaGetSymbolAddress((void**)&e0, g_esrc0);
    cudaGetSymbolAddress((void**)&e1, g_esrc1);
    cudaGetSymbolAddress((void**)&e2, g_esrc2);

    float* stats0 = stats;
    float* stats1 = stats + 2 * DH;
    int* deg = cnt;
    int* cur = cnt + NTOT;

    // --- combined CSR build + zeroing (5 launches total) ---
    cudaMemsetAsync(cnt, 0, sizeof(int) * 2 * NTOT, 0);
    cudaMemsetAsync(stats, 0, sizeof(float) * 4 * DH, 0);
    k_hist_all<<<(NETOT + 255) / 256, 256>>>(dst0, dst1, dst2, deg);
    k_scan3<<<3, 1024>>>(deg, off0, off1, off2);
    k_bucket_all<<<(NETOT + 255) / 256, 256>>>(src0, dst0, src1, dst1, src2, dst2,
                                               off0, off1, off2, cur, e0, e1, e2);

    // --- layer 0: IN=128 -> H=256, M = 25600 ---
    k_gather<DIN, false><<<NDST0 * 32 / 256, 256>>>(x, e0, off0, agg, NDST0,
                                                    nullptr, nullptr, nullptr, 0.f);
    {
        dim3 g(NDST0 / 128, DH / 128);
        k_gemm_tc<<<g, 256>>>(agg, x, Wl0, Wr0, bl0, h1, NDST0, DIN, DH, stats0,
                              nullptr, nullptr, nullptr, 0.f);
    }

    // --- layer 1: H=256 -> H=256, M = 5120 (BN0 fused into consumers) ---
    k_gather<DH, true><<<NDST1 * 32 / 256, 256>>>(h1, e1, off1, agg, NDST1,
                                                  stats0, gamma0, beta0, 1.0f / NDST0);
    {
        dim3 g(NDST1 / 128, DH / 128);
        k_gemm_tc<<<g, 256>>>(agg, h1, Wl1, Wr1, bl1, h2, NDST1, DH, DH, stats1,
                              stats0, gamma0, beta0, 1.0f / NDST0);
    }

    // --- layer 2: H=256 -> OUT=64, M = 1024 (BN1 fused into consumers) ---
    k_gather<DH, true><<<NDST2 * 32 / 256, 256>>>(h2, e2, off2, agg, NDST2,
                                                  stats1, gamma1, beta1, 1.0f / NDST1);
    {
        dim3 g(NDST2 / 64, DOUT / 64);
        k_gemm64<<<g, 256>>>(agg, h2, Wl2, Wr2, bl2, out, NDST2, DH, DOUT,
                             stats1, gamma1, beta1, 1.0f / NDST1);
    }
}

// round 6
// speedup vs baseline: 1.7830x; 1.0835x over previous
#include <cuda_runtime.h>

// ---------------- problem constants ------------------------------------------
#define NDST0 25600
#define NDST1 5120
#define NDST2 1024
#define NTOT  (NDST0 + NDST1 + NDST2)
#define NE0   256000
#define NE1   51200
#define NE2   10240
#define NETOT (NE0 + NE1 + NE2)
#define DIN   128
#define DH    256
#define DOUT  64

// ---------------- device scratch (no allocations allowed) --------------------
__device__ float g_agg[NDST0 * DIN];      // gather output (reused per layer)
__device__ float g_h1[NDST0 * DH];        // layer-0 raw GEMM output (pre-BN)
__device__ float g_h2[NDST1 * DH];        // layer-1 raw GEMM output (pre-BN)
// single zero-init region: [deg | cur | stats0 | stats1]
__device__ int   g_zero[2 * NTOT + 4 * DH];
__device__ int   g_off0[NDST0 + 1];
__device__ int   g_off1[NDST1 + 1];
__device__ int   g_off2[NDST2 + 1];
__device__ int   g_esrc0[NE0];
__device__ int   g_esrc1[NE1];
__device__ int   g_esrc2[NE2];

// ---------------- combined CSR build -----------------------------------------
__global__ void k_hist_all(const int* __restrict__ d0, const int* __restrict__ d1,
                           const int* __restrict__ d2, int* __restrict__ deg) {
    int e = blockIdx.x * blockDim.x + threadIdx.x;
    if (e < NE0)                 atomicAdd(&deg[d0[e]], 1);
    else if (e < NE0 + NE1)      atomicAdd(&deg[NDST0 + d1[e - NE0]], 1);
    else if (e < NETOT)          atomicAdd(&deg[NDST0 + NDST1 + d2[e - NE0 - NE1]], 1);
}

__global__ void k_scan3(const int* __restrict__ deg, int* __restrict__ off0,
                        int* __restrict__ off1, int* __restrict__ off2) {
    __shared__ int part[1024];
    int b = blockIdx.x, t = threadIdx.x;
    int n    = (b == 0) ? NDST0 : (b == 1) ? NDST1 : NDST2;
    int base = (b == 0) ? 0 : (b == 1) ? NDST0 : NDST0 + NDST1;
    int* off = (b == 0) ? off0 : (b == 1) ? off1 : off2;
    const int* d = deg + base;

    int chunk = (n + 1023) >> 10;
    int lo = t * chunk, hi = min(lo + chunk, n);
    int s = 0;
    for (int i = lo; i < hi; i++) s += d[i];
    part[t] = s;
    __syncthreads();
    for (int st = 1; st < 1024; st <<= 1) {
        int v = (t >= st) ? part[t - st] : 0;
        __syncthreads();
        part[t] += v;
        __syncthreads();
    }
    int run = t ? part[t - 1] : 0;
    for (int i = lo; i < hi; i++) { off[i] = run; run += d[i]; }
    if (t == 1023) off[n] = part[1023];
}

__global__ void k_bucket_all(const int* __restrict__ s0, const int* __restrict__ d0,
                             const int* __restrict__ s1, const int* __restrict__ d1,
                             const int* __restrict__ s2, const int* __restrict__ d2,
                             const int* __restrict__ off0, const int* __restrict__ off1,
                             const int* __restrict__ off2, int* __restrict__ cur,
                             int* __restrict__ e0, int* __restrict__ e1, int* __restrict__ e2) {
    int e = blockIdx.x * blockDim.x + threadIdx.x;
    if (e < NE0) {
        int d = d0[e];
        e0[off0[d] + atomicAdd(&cur[d], 1)] = s0[e];
    } else if (e < NE0 + NE1) {
        int i = e - NE0, d = d1[i];
        e1[off1[d] + atomicAdd(&cur[NDST0 + d], 1)] = s1[i];
    } else if (e < NETOT) {
        int i = e - NE0 - NE1, d = d2[i];
        e2[off2[d] + atomicAdd(&cur[NDST0 + NDST1 + d], 1)] = s2[i];
    }
}

// ---------------- gather mean (optionally fused BN+ReLU on inputs) ------------
template <int D, bool BN>
__global__ void k_gather(const float* __restrict__ x, const int* __restrict__ esrc,
                         const int* __restrict__ off, float* __restrict__ agg, int nDst,
                         const float* __restrict__ stats, const float* __restrict__ gamma,
                         const float* __restrict__ beta, float invM) {
    constexpr int R = D / 128;
    __shared__ float saa[D], sbb[D];
    int lane = threadIdx.x & 31;
    if (BN) {
        int t = threadIdx.x;
        if (t < D) {
            float m = stats[t] * invM;
            float v = stats[t + D] * invM - m * m;
            float a = gamma[t] * rsqrtf(v + 1e-5f);
            saa[t] = a;
            sbb[t] = beta[t] - m * a;
        }
        __syncthreads();
    }
    int w = (blockIdx.x * blockDim.x + threadIdx.x) >> 5;
    if (w >= nDst) return;

    float4 ca[R], cb[R];
    if (BN) {
#pragma unroll
        for (int r = 0; r < R; r++) {
            ca[r] = *(const float4*)&saa[4 * lane + 128 * r];
            cb[r] = *(const float4*)&sbb[4 * lane + 128 * r];
        }
    }

    int beg = off[w], end = off[w + 1];
    float4 acc[R];
#pragma unroll
    for (int r = 0; r < R; r++) acc[r] = make_float4(0.f, 0.f, 0.f, 0.f);

    int e = beg;
    for (; e + 1 < end; e += 2) {
        const float4* p0 = (const float4*)(x + (long)esrc[e] * D) + lane;
        const float4* p1 = (const float4*)(x + (long)esrc[e + 1] * D) + lane;
        float4 v0[R], v1[R];
#pragma unroll
        for (int r = 0; r < R; r++) { v0[r] = p0[r * 32]; v1[r] = p1[r * 32]; }
#pragma unroll
        for (int r = 0; r < R; r++) {
            if (BN) {
                v0[r].x = fmaxf(fmaf(v0[r].x, ca[r].x, cb[r].x), 0.f);
                v0[r].y = fmaxf(fmaf(v0[r].y, ca[r].y, cb[r].y), 0.f);
                v0[r].z = fmaxf(fmaf(v0[r].z, ca[r].z, cb[r].z), 0.f);
                v0[r].w = fmaxf(fmaf(v0[r].w, ca[r].w, cb[r].w), 0.f);
                v1[r].x = fmaxf(fmaf(v1[r].x, ca[r].x, cb[r].x), 0.f);
                v1[r].y = fmaxf(fmaf(v1[r].y, ca[r].y, cb[r].y), 0.f);
                v1[r].z = fmaxf(fmaf(v1[r].z, ca[r].z, cb[r].z), 0.f);
                v1[r].w = fmaxf(fmaf(v1[r].w, ca[r].w, cb[r].w), 0.f);
            }
            acc[r].x += v0[r].x + v1[r].x;
            acc[r].y += v0[r].y + v1[r].y;
            acc[r].z += v0[r].z + v1[r].z;
            acc[r].w += v0[r].w + v1[r].w;
        }
    }
    if (e < end) {
        const float4* p0 = (const float4*)(x + (long)esrc[e] * D) + lane;
#pragma unroll
        for (int r = 0; r < R; r++) {
            float4 v = p0[r * 32];
            if (BN) {
                v.x = fmaxf(fmaf(v.x, ca[r].x, cb[r].x), 0.f);
                v.y = fmaxf(fmaf(v.y, ca[r].y, cb[r].y), 0.f);
                v.z = fmaxf(fmaf(v.z, ca[r].z, cb[r].z), 0.f);
                v.w = fmaxf(fmaf(v.w, ca[r].w, cb[r].w), 0.f);
            }
            acc[r].x += v.x; acc[r].y += v.y; acc[r].z += v.z; acc[r].w += v.w;
        }
    }
    int c = end - beg;
    float inv = 1.0f / (float)(c > 0 ? c : 1);
    float4* o = (float4*)(agg + (long)w * D) + lane;
#pragma unroll
    for (int r = 0; r < R; r++) {
        acc[r].x *= inv; acc[r].y *= inv; acc[r].z *= inv; acc[r].w *= inv;
        o[r * 32] = acc[r];
    }
}

// ---------------- tf32 helpers ------------------------------------------------
__device__ __forceinline__ float tf32r(float x) {
    unsigned u;
    asm("cvt.rna.tf32.f32 %0, %1;" : "=r"(u) : "f"(x));
    return __uint_as_float(u);
}

__device__ __forceinline__ void mma_tf32(float (&d)[4], const unsigned (&a)[4],
                                         const unsigned (&b)[2]) {
    asm volatile(
        "mma.sync.aligned.m16n8k8.row.col.f32.tf32.tf32.f32 "
        "{%0,%1,%2,%3}, {%4,%5,%6,%7}, {%8,%9}, {%0,%1,%2,%3};\n"
        : "+f"(d[0]), "+f"(d[1]), "+f"(d[2]), "+f"(d[3])
        : "r"(a[0]), "r"(a[1]), "r"(a[2]), "r"(a[3]), "r"(b[0]), "r"(b[1]));
}

// ---------------- tensor-core fused dual GEMM (double-buffered) ---------------
// C = tf32(A1)@tf32(B1) + bias + tf32(bnrelu?(A2))@tf32(B2)
// Block 128x128, 8 warps (2x4), warp tile 64x32, BK=16, 2-stage smem pipeline.
// As m-major [128][20] (pad 20 -> float4-aligned rows, conflict-free frag reads).
// Bs [16][136] (pad 136 -> conflict-free frag reads). Wide STS.128 tile stores.
#define TCBK 16
__global__ __launch_bounds__(256, 2)
void k_gemm_tc(const float* __restrict__ A1, const float* __restrict__ A2,
               const float* __restrict__ B1, const float* __restrict__ B2,
               const float* __restrict__ bias, float* __restrict__ C,
               int M, int K0, int N, float* __restrict__ stats,
               const float* __restrict__ bnst, const float* __restrict__ bng,
               const float* __restrict__ bnb, float bnInv) {
    __shared__ float As[2][128][20];
    __shared__ float Bs[2][TCBK][136];
    __shared__ float s_sum[128];
    __shared__ float s_sq[128];
    __shared__ float s_aa[256];
    __shared__ float s_bb[256];

    const int tid  = threadIdx.x;
    const int lane = tid & 31;
    const int warp = tid >> 5;
    const int mw = (warp & 1) * 64;
    const int nw = (warp >> 1) * 32;
    const int m0 = blockIdx.x * 128, n0 = blockIdx.y * 128;
    const int q = lane & 3, r = lane >> 2;

    const int ar = tid >> 1;          // A-load row (0..127)
    const int ak = (tid & 1) * 8;     // A-load k base (0 or 8)
    const int bk = tid >> 4;          // B-load k (0..15)
    const int bc = (tid & 15) * 8;    // B-load col base

    const bool hasBN = (bnst != nullptr);
    if (hasBN && tid < 256) {
        float m = bnst[tid] * bnInv;
        float v = bnst[tid + 256] * bnInv - m * m;
        float a = bng[tid] * rsqrtf(v + 1e-5f);
        s_aa[tid] = a;
        s_bb[tid] = bnb[tid] - m * a;
    }
    if (tid < 128) { s_sum[tid] = 0.f; s_sq[tid] = 0.f; }

    float acc[4][4][4];
#pragma unroll
    for (int mf = 0; mf < 4; mf++)
#pragma unroll
        for (int nf = 0; nf < 4; nf++)
#pragma unroll
            for (int c = 0; c < 4; c++) acc[mf][nf][c] = 0.f;

    const int K2 = 2 * K0;

    auto ldTile = [&](int kb, float4& a0, float4& a1, float4& b0, float4& b1) {
        const float* A = (kb < K0) ? A1 : A2;
        const float* B = (kb < K0) ? B1 : B2;
        int ko = (kb < K0) ? kb : kb - K0;
        const float* ap = A + (long)(m0 + ar) * K0 + ko + ak;
        a0 = *(const float4*)ap;
        a1 = *(const float4*)(ap + 4);
        const float* bp = B + (long)(ko + bk) * N + n0 + bc;
        b0 = *(const float4*)bp;
        b1 = *(const float4*)(bp + 4);
    };

    auto stTile = [&](int kb, int p, float4 a0, float4 a1, float4 b0, float4 b1) {
        int ko = (kb < K0) ? kb : kb - K0;
        float av[8] = {a0.x, a0.y, a0.z, a0.w, a1.x, a1.y, a1.z, a1.w};
        if (hasBN && kb >= K0) {
            int c = ko + ak;
#pragma unroll
            for (int j = 0; j < 8; j++)
                av[j] = fmaxf(fmaf(av[j], s_aa[c + j], s_bb[c + j]), 0.f);
        }
        float4 c0 = make_float4(tf32r(av[0]), tf32r(av[1]), tf32r(av[2]), tf32r(av[3]));
        float4 c1 = make_float4(tf32r(av[4]), tf32r(av[5]), tf32r(av[6]), tf32r(av[7]));
        *(float4*)&As[p][ar][ak]     = c0;
        *(float4*)&As[p][ar][ak + 4] = c1;
        float4 d0 = make_float4(tf32r(b0.x), tf32r(b0.y), tf32r(b0.z), tf32r(b0.w));
        float4 d1 = make_float4(tf32r(b1.x), tf32r(b1.y), tf32r(b1.z), tf32r(b1.w));
        *(float4*)&Bs[p][bk][bc]     = d0;
        *(float4*)&Bs[p][bk][bc + 4] = d1;
    };

    // prologue
    float4 pa0, pa1, pb0, pb1;
    ldTile(0, pa0, pa1, pb0, pb1);
    __syncthreads();                 // BN coeffs + s_sum init visible
    stTile(0, 0, pa0, pa1, pb0, pb1);
    __syncthreads();

    int p = 0;
    for (int kb = 0; kb < K2; kb += TCBK) {
        int nx = kb + TCBK;
        float4 na0, na1, nb0, nb1;
        if (nx < K2) ldTile(nx, na0, na1, nb0, nb1);

#pragma unroll
        for (int ks = 0; ks < TCBK; ks += 8) {
            unsigned a[4][4], b[4][2];
#pragma unroll
            for (int mf = 0; mf < 4; mf++) {
                int m = mw + mf * 16 + r;
                a[mf][0] = __float_as_uint(As[p][m][ks + q]);
                a[mf][1] = __float_as_uint(As[p][m + 8][ks + q]);
                a[mf][2] = __float_as_uint(As[p][m][ks + q + 4]);
                a[mf][3] = __float_as_uint(As[p][m + 8][ks + q + 4]);
            }
#pragma unroll
            for (int nf = 0; nf < 4; nf++) {
                int n = nw + nf * 8 + r;
                b[nf][0] = __float_as_uint(Bs[p][ks + q][n]);
                b[nf][1] = __float_as_uint(Bs[p][ks + q + 4][n]);
            }
#pragma unroll
            for (int mf = 0; mf < 4; mf++)
#pragma unroll
                for (int nf = 0; nf < 4; nf++)
                    mma_tf32(acc[mf][nf], a[mf], b[nf]);
        }

        if (nx < K2) stTile(nx, p ^ 1, na0, na1, nb0, nb1);
        __syncthreads();
        p ^= 1;
    }

    float bs0[4], bs1[4];
#pragma unroll
    for (int nf = 0; nf < 4; nf++) {
        int c = n0 + nw + nf * 8 + 2 * q;
        bs0[nf] = bias[c];
        bs1[nf] = bias[c + 1];
    }

    float csum0[4] = {}, csum1[4] = {}, csq0[4] = {}, csq1[4] = {};
#pragma unroll
    for (int mf = 0; mf < 4; mf++) {
        int row0 = m0 + mw + mf * 16 + r;
#pragma unroll
        for (int nf = 0; nf < 4; nf++) {
            int col = n0 + nw + nf * 8 + 2 * q;
            float v0 = acc[mf][nf][0] + bs0[nf];
            float v1 = acc[mf][nf][1] + bs1[nf];
            float v2 = acc[mf][nf][2] + bs0[nf];
            float v3 = acc[mf][nf][3] + bs1[nf];
            *(float2*)(C + (long)row0 * N + col)       = make_float2(v0, v1);
            *(float2*)(C + (long)(row0 + 8) * N + col) = make_float2(v2, v3);
            csum0[nf] += v0 + v2;
            csum1[nf] += v1 + v3;
            csq0[nf]  += v0 * v0 + v2 * v2;
            csq1[nf]  += v1 * v1 + v3 * v3;
        }
    }

    if (stats) {
#pragma unroll
        for (int nf = 0; nf < 4; nf++) {
            int cl = nw + nf * 8 + 2 * q;
            atomicAdd(&s_sum[cl],     csum0[nf]);
            atomicAdd(&s_sum[cl + 1], csum1[nf]);
            atomicAdd(&s_sq[cl],      csq0[nf]);
            atomicAdd(&s_sq[cl + 1],  csq1[nf]);
        }
        __syncthreads();
        if (tid < 128) {
            atomicAdd(&stats[n0 + tid],     s_sum[tid]);
            atomicAdd(&stats[N + n0 + tid], s_sq[tid]);
        }
    }
}

// ---------------- 64x64 FFMA dual GEMM for the final layer (BN on A2) ---------
__global__ void k_gemm64(const float* __restrict__ A1, const float* __restrict__ A2,
                         const float* __restrict__ B1, const float* __restrict__ B2,
                         const float* __restrict__ bias, float* __restrict__ C,
                         int M, int K0, int N,
                         const float* __restrict__ bnst, const float* __restrict__ bng,
                         const float* __restrict__ bnb, float bnInv) {
    __shared__ float As[16][68];
    __shared__ float Bs[16][68];
    __shared__ float s_aa[256];
    __shared__ float s_bb[256];
    const int tid = threadIdx.x;
    const int tx = tid & 15, ty = tid >> 4;
    const int m0 = blockIdx.x * 64, n0 = blockIdx.y * 64;
    const int lr = tid >> 2;
    const int lk = (tid & 3) * 4;
    const int bk = tid >> 4;
    const int bn = (tid & 15) * 4;

    if (tid < 256) {
        float m = bnst[tid] * bnInv;
        float v = bnst[tid + 256] * bnInv - m * m;
        float a = bng[tid] * rsqrtf(v + 1e-5f);
        s_aa[tid] = a;
        s_bb[tid] = bnb[tid] - m * a;
    }
    __syncthreads();

    float acc[4][4] = {};
    const int K2 = 2 * K0;
    for (int kb = 0; kb < K2; kb += 16) {
        const float* A = (kb < K0) ? A1 : A2;
        const float* B = (kb < K0) ? B1 : B2;
        const int ko   = (kb < K0) ? kb : kb - K0;

        float4 av = *(const float4*)(A + (long)(m0 + lr) * K0 + ko + lk);
        if (kb >= K0) {
            int c = ko + lk;
            av.x = fmaxf(fmaf(av.x, s_aa[c + 0], s_bb[c + 0]), 0.f);
            av.y = fmaxf(fmaf(av.y, s_aa[c + 1], s_bb[c + 1]), 0.f);
            av.z = fmaxf(fmaf(av.z, s_aa[c + 2], s_bb[c + 2]), 0.f);
            av.w = fmaxf(fmaf(av.w, s_aa[c + 3], s_bb[c + 3]), 0.f);
        }
        As[lk + 0][lr] = av.x;
        As[lk + 1][lr] = av.y;
        As[lk + 2][lr] = av.z;
        As[lk + 3][lr] = av.w;
        *(float4*)&Bs[bk][bn] = *(const float4*)(B + (long)(ko + bk) * N + n0 + bn);
        __syncthreads();

#pragma unroll
        for (int k = 0; k < 16; k++) {
            float a[4], b[4];
#pragma unroll
            for (int i = 0; i < 4; i++) a[i] = As[k][ty * 4 + i];
#pragma unroll
            for (int j = 0; j < 4; j++) b[j] = Bs[k][tx * 4 + j];
#pragma unroll
            for (int i = 0; i < 4; i++)
#pragma unroll
                for (int j = 0; j < 4; j++) acc[i][j] += a[i] * b[j];
        }
        __syncthreads();
    }

#pragma unroll
    for (int i = 0; i < 4; i++)
#pragma unroll
        for (int j = 0; j < 4; j++)
            C[(long)(m0 + ty * 4 + i) * N + n0 + tx * 4 + j] =
                acc[i][j] + bias[n0 + tx * 4 + j];
}

// ---------------- launch ------------------------------------------------------
extern "C" void kernel_launch(void* const* d_in, const int* in_sizes, int n_in,
                              void* d_out, int out_size) {
    const float* x      = (const float*)d_in[0];
    const float* Wl0    = (const float*)d_in[1];
    const float* bl0    = (const float*)d_in[2];
    const float* Wr0    = (const float*)d_in[3];
    const float* Wl1    = (const float*)d_in[4];
    const float* bl1    = (const float*)d_in[5];
    const float* Wr1    = (const float*)d_in[6];
    const float* Wl2    = (const float*)d_in[7];
    const float* bl2    = (const float*)d_in[8];
    const float* Wr2    = (const float*)d_in[9];
    const float* gamma0 = (const float*)d_in[10];
    const float* beta0  = (const float*)d_in[11];
    const float* gamma1 = (const float*)d_in[12];
    const float* beta1  = (const float*)d_in[13];
    const int* src0 = (const int*)d_in[14];
    const int* dst0 = (const int*)d_in[15];
    const int* src1 = (const int*)d_in[16];
    const int* dst1 = (const int*)d_in[17];
    const int* src2 = (const int*)d_in[18];
    const int* dst2 = (const int*)d_in[19];
    float* out = (float*)d_out;

    float *agg, *h1, *h2;
    int *zero, *off0, *off1, *off2, *e0, *e1, *e2;
    cudaGetSymbolAddress((void**)&agg, g_agg);
    cudaGetSymbolAddress((void**)&h1, g_h1);
    cudaGetSymbolAddress((void**)&h2, g_h2);
    cudaGetSymbolAddress((void**)&zero, g_zero);
    cudaGetSymbolAddress((void**)&off0, g_off0);
    cudaGetSymbolAddress((void**)&off1, g_off1);
    cudaGetSymbolAddress((void**)&off2, g_off2);
    cudaGetSymbolAddress((void**)&e0, g_esrc0);
    cudaGetSymbolAddress((void**)&e1, g_esrc1);
    cudaGetSymbolAddress((void**)&e2, g_esrc2);

    int* deg = zero;
    int* cur = zero + NTOT;
    float* stats0 = (float*)(zero + 2 * NTOT);
    float* stats1 = stats0 + 2 * DH;

    // --- combined CSR build + zeroing (4 launches total) ---
    cudaMemsetAsync(zero, 0, sizeof(int) * (2 * NTOT + 4 * DH), 0);
    k_hist_all<<<(NETOT + 255) / 256, 256>>>(dst0, dst1, dst2, deg);
    k_scan3<<<3, 1024>>>(deg, off0, off1, off2);
    k_bucket_all<<<(NETOT + 255) / 256, 256>>>(src0, dst0, src1, dst1, src2, dst2,
                                               off0, off1, off2, cur, e0, e1, e2);

    // --- layer 0: IN=128 -> H=256, M = 25600 ---
    k_gather<DIN, false><<<NDST0 * 32 / 256, 256>>>(x, e0, off0, agg, NDST0,
                                                    nullptr, nullptr, nullptr, 0.f);
    {
        dim3 g(NDST0 / 128, DH / 128);
        k_gemm_tc<<<g, 256>>>(agg, x, Wl0, Wr0, bl0, h1, NDST0, DIN, DH, stats0,
                              nullptr, nullptr, nullptr, 0.f);
    }

    // --- layer 1: H=256 -> H=256, M = 5120 (BN0 fused into consumers) ---
    k_gather<DH, true><<<NDST1 * 32 / 256, 256>>>(h1, e1, off1, agg, NDST1,
                                                  stats0, gamma0, beta0, 1.0f / NDST0);
    {
        dim3 g(NDST1 / 128, DH / 128);
        k_gemm_tc<<<g, 256>>>(agg, h1, Wl1, Wr1, bl1, h2, NDST1, DH, DH, stats1,
                              stats0, gamma0, beta0, 1.0f / NDST0);
    }

    // --- layer 2: H=256 -> OUT=64, M = 1024 (BN1 fused into consumers) ---
    k_gather<DH, true><<<NDST2 * 32 / 256, 256>>>(h2, e2, off2, agg, NDST2,
                                                  stats1, gamma1, beta1, 1.0f / NDST1);
    {
        dim3 g(NDST2 / 64, DOUT / 64);
        k_gemm64<<<g, 256>>>(agg, h2, Wl2, Wr2, bl2, out, NDST2, DH, DOUT,
                             stats1, gamma1, beta1, 1.0f / NDST1);
    }
}

// round 7
// speedup vs baseline: 1.9881x; 1.1151x over previous
#include <cuda_runtime.h>

// ---------------- problem constants ------------------------------------------
#define NDST0 25600
#define NDST1 5120
#define NDST2 1024
#define NTOT  (NDST0 + NDST1 + NDST2)
#define NE0   256000
#define NE1   51200
#define NE2   10240
#define NETOT (NE0 + NE1 + NE2)
#define DIN   128
#define DH    256
#define DOUT  64

// ---------------- device scratch (no allocations allowed) --------------------
__device__ float g_agg[NDST0 * DIN];      // gather output (reused per layer)
__device__ float g_h1[NDST0 * DH];        // layer-0 raw GEMM output (pre-BN)
__device__ float g_h2[NDST1 * DH];        // layer-1 raw GEMM output (pre-BN)
// single zero-init region: [deg | cur | stats0 | stats1]
__device__ int   g_zero[2 * NTOT + 4 * DH];
__device__ int   g_off0[NDST0 + 1];
__device__ int   g_off1[NDST1 + 1];
__device__ int   g_off2[NDST2 + 1];
__device__ int   g_esrc0[NE0];
__device__ int   g_esrc1[NE1];
__device__ int   g_esrc2[NE2];

// ---------------- combined CSR build -----------------------------------------
__global__ void k_hist_all(const int* __restrict__ d0, const int* __restrict__ d1,
                           const int* __restrict__ d2, int* __restrict__ deg) {
    int e = blockIdx.x * blockDim.x + threadIdx.x;
    if (e < NE0)                 atomicAdd(&deg[d0[e]], 1);
    else if (e < NE0 + NE1)      atomicAdd(&deg[NDST0 + d1[e - NE0]], 1);
    else if (e < NETOT)          atomicAdd(&deg[NDST0 + NDST1 + d2[e - NE0 - NE1]], 1);
}

// per-thread contiguous chunk, int4-vectorized loads/stores
__global__ void k_scan3(const int* __restrict__ deg, int* __restrict__ off0,
                        int* __restrict__ off1, int* __restrict__ off2) {
    __shared__ int part[1024];
    int b = blockIdx.x, t = threadIdx.x;
    int n    = (b == 0) ? NDST0 : (b == 1) ? NDST1 : NDST2;
    int base = (b == 0) ? 0 : (b == 1) ? NDST0 : NDST0 + NDST1;
    int* off = (b == 0) ? off0 : (b == 1) ? off1 : off2;
    const int* d = deg + base;

    int chunk = ((n + 1023) >> 10 + 0);            // elems per thread (ceil)
    chunk = ((n + 1023) >> 10);
    chunk = (chunk + 3) & ~3;                      // round to 4 for int4
    int lo = t * chunk, hi = min(lo + chunk, n);

    int s = 0;
    int i = lo;
    for (; i + 4 <= hi; i += 4) {
        int4 v = *(const int4*)(d + i);
        s += v.x + v.y + v.z + v.w;
    }
    for (; i < hi; i++) s += d[i];
    part[t] = s;
    __syncthreads();
    for (int st = 1; st < 1024; st <<= 1) {
        int v = (t >= st) ? part[t - st] : 0;
        __syncthreads();
        part[t] += v;
        __syncthreads();
    }
    int run = t ? part[t - 1] : 0;
    i = lo;
    for (; i + 4 <= hi; i += 4) {
        int4 v = *(const int4*)(d + i);
        int4 o;
        o.x = run;           o.y = run + v.x;
        o.z = o.y + v.y;     o.w = o.z + v.z;
        run = o.w + v.w;
        *(int4*)(off + i) = o;
    }
    for (; i < hi; i++) { off[i] = run; run += d[i]; }
    if (t == 1023) off[n] = part[1023];
}

__global__ void k_bucket_all(const int* __restrict__ s0, const int* __restrict__ d0,
                             const int* __restrict__ s1, const int* __restrict__ d1,
                             const int* __restrict__ s2, const int* __restrict__ d2,
                             const int* __restrict__ off0, const int* __restrict__ off1,
                             const int* __restrict__ off2, int* __restrict__ cur,
                             int* __restrict__ e0, int* __restrict__ e1, int* __restrict__ e2) {
    int e = blockIdx.x * blockDim.x + threadIdx.x;
    if (e < NE0) {
        int d = d0[e];
        e0[off0[d] + atomicAdd(&cur[d], 1)] = s0[e];
    } else if (e < NE0 + NE1) {
        int i = e - NE0, d = d1[i];
        e1[off1[d] + atomicAdd(&cur[NDST0 + d], 1)] = s1[i];
    } else if (e < NETOT) {
        int i = e - NE0 - NE1, d = d2[i];
        e2[off2[d] + atomicAdd(&cur[NDST0 + NDST1 + d], 1)] = s2[i];
    }
}

// ---------------- gather mean (optionally fused BN+ReLU on inputs) ------------
template <int D, bool BN>
__global__ void k_gather(const float* __restrict__ x, const int* __restrict__ esrc,
                         const int* __restrict__ off, float* __restrict__ agg, int nDst,
                         const float* __restrict__ stats, const float* __restrict__ gamma,
                         const float* __restrict__ beta, float invM) {
    constexpr int R = D / 128;
    __shared__ float saa[D], sbb[D];
    int lane = threadIdx.x & 31;
    if (BN) {
        int t = threadIdx.x;
        if (t < D) {
            float m = stats[t] * invM;
            float v = stats[t + D] * invM - m * m;
            float a = gamma[t] * rsqrtf(v + 1e-5f);
            saa[t] = a;
            sbb[t] = beta[t] - m * a;
        }
        __syncthreads();
    }
    int w = (blockIdx.x * blockDim.x + threadIdx.x) >> 5;
    if (w >= nDst) return;

    float4 ca[R], cb[R];
    if (BN) {
#pragma unroll
        for (int r = 0; r < R; r++) {
            ca[r] = *(const float4*)&saa[4 * lane + 128 * r];
            cb[r] = *(const float4*)&sbb[4 * lane + 128 * r];
        }
    }

    int beg = off[w], end = off[w + 1];
    float4 acc[R];
#pragma unroll
    for (int r = 0; r < R; r++) acc[r] = make_float4(0.f, 0.f, 0.f, 0.f);

    int e = beg;
    for (; e + 1 < end; e += 2) {
        const float4* p0 = (const float4*)(x + (long)esrc[e] * D) + lane;
        const float4* p1 = (const float4*)(x + (long)esrc[e + 1] * D) + lane;
        float4 v0[R], v1[R];
#pragma unroll
        for (int r = 0; r < R; r++) { v0[r] = p0[r * 32]; v1[r] = p1[r * 32]; }
#pragma unroll
        for (int r = 0; r < R; r++) {
            if (BN) {
                v0[r].x = fmaxf(fmaf(v0[r].x, ca[r].x, cb[r].x), 0.f);
                v0[r].y = fmaxf(fmaf(v0[r].y, ca[r].y, cb[r].y), 0.f);
                v0[r].z = fmaxf(fmaf(v0[r].z, ca[r].z, cb[r].z), 0.f);
                v0[r].w = fmaxf(fmaf(v0[r].w, ca[r].w, cb[r].w), 0.f);
                v1[r].x = fmaxf(fmaf(v1[r].x, ca[r].x, cb[r].x), 0.f);
                v1[r].y = fmaxf(fmaf(v1[r].y, ca[r].y, cb[r].y), 0.f);
                v1[r].z = fmaxf(fmaf(v1[r].z, ca[r].z, cb[r].z), 0.f);
                v1[r].w = fmaxf(fmaf(v1[r].w, ca[r].w, cb[r].w), 0.f);
            }
            acc[r].x += v0[r].x + v1[r].x;
            acc[r].y += v0[r].y + v1[r].y;
            acc[r].z += v0[r].z + v1[r].z;
            acc[r].w += v0[r].w + v1[r].w;
        }
    }
    if (e < end) {
        const float4* p0 = (const float4*)(x + (long)esrc[e] * D) + lane;
#pragma unroll
        for (int r = 0; r < R; r++) {
            float4 v = p0[r * 32];
            if (BN) {
                v.x = fmaxf(fmaf(v.x, ca[r].x, cb[r].x), 0.f);
                v.y = fmaxf(fmaf(v.y, ca[r].y, cb[r].y), 0.f);
                v.z = fmaxf(fmaf(v.z, ca[r].z, cb[r].z), 0.f);
                v.w = fmaxf(fmaf(v.w, ca[r].w, cb[r].w), 0.f);
            }
            acc[r].x += v.x; acc[r].y += v.y; acc[r].z += v.z; acc[r].w += v.w;
        }
    }
    int c = end - beg;
    float inv = 1.0f / (float)(c > 0 ? c : 1);
    float4* o = (float4*)(agg + (long)w * D) + lane;
#pragma unroll
    for (int r = 0; r < R; r++) {
        acc[r].x *= inv; acc[r].y *= inv; acc[r].z *= inv; acc[r].w *= inv;
        o[r * 32] = acc[r];
    }
}

// ---------------- tf32 helpers ------------------------------------------------
__device__ __forceinline__ float tf32r(float x) {
    unsigned u;
    asm("cvt.rna.tf32.f32 %0, %1;" : "=r"(u) : "f"(x));
    return __uint_as_float(u);
}

__device__ __forceinline__ void mma_tf32(float (&d)[4], const unsigned (&a)[4],
                                         const unsigned (&b)[2]) {
    asm volatile(
        "mma.sync.aligned.m16n8k8.row.col.f32.tf32.tf32.f32 "
        "{%0,%1,%2,%3}, {%4,%5,%6,%7}, {%8,%9}, {%0,%1,%2,%3};\n"
        : "+f"(d[0]), "+f"(d[1]), "+f"(d[2]), "+f"(d[3])
        : "r"(a[0]), "r"(a[1]), "r"(a[2]), "r"(a[3]), "r"(b[0]), "r"(b[1]));
}

// ---------------- tensor-core fused dual GEMM (double-buffered) ---------------
// C = tf32(A1)@tf32(B1) + bias + tf32(bnrelu?(A2))@tf32(B2)
// Block MTx128 (MT=128 or 64), 8 warps (2x4), warp tile (MT/2)x32, BK=16.
#define TCBK 16
template <int MT>
__global__ __launch_bounds__(256, 2)
void k_gemm_tc(const float* __restrict__ A1, const float* __restrict__ A2,
               const float* __restrict__ B1, const float* __restrict__ B2,
               const float* __restrict__ bias, float* __restrict__ C,
               int M, int K0, int N, float* __restrict__ stats,
               const float* __restrict__ bnst, const float* __restrict__ bng,
               const float* __restrict__ bnb, float bnInv) {
    constexpr int MF = MT / 32;                  // m fragments per warp (4 or 2)
    __shared__ float As[2][MT][20];
    __shared__ float Bs[2][TCBK][136];
    __shared__ float s_sum[128];
    __shared__ float s_sq[128];
    __shared__ float s_aa[256];
    __shared__ float s_bb[256];

    const int tid  = threadIdx.x;
    const int lane = tid & 31;
    const int warp = tid >> 5;
    const int mw = (warp & 1) * (MT / 2);
    const int nw = (warp >> 1) * 32;
    const int m0 = blockIdx.x * MT, n0 = blockIdx.y * 128;
    const int q = lane & 3, r = lane >> 2;

    // A-load mapping: MT=128 -> 8 floats/thread, MT=64 -> 4 floats/thread
    const int ar = (MT == 128) ? (tid >> 1) : (tid >> 2);
    const int ak = (MT == 128) ? ((tid & 1) * 8) : ((tid & 3) * 4);
    const int bk = tid >> 4;          // B-load k (0..15)
    const int bc = (tid & 15) * 8;    // B-load col base

    const bool hasBN = (bnst != nullptr);
    if (hasBN && tid < 256) {
        float m = bnst[tid] * bnInv;
        float v = bnst[tid + 256] * bnInv - m * m;
        float a = bng[tid] * rsqrtf(v + 1e-5f);
        s_aa[tid] = a;
        s_bb[tid] = bnb[tid] - m * a;
    }
    if (tid < 128) { s_sum[tid] = 0.f; s_sq[tid] = 0.f; }

    float acc[MF][4][4];
#pragma unroll
    for (int mf = 0; mf < MF; mf++)
#pragma unroll
        for (int nf = 0; nf < 4; nf++)
#pragma unroll
            for (int c = 0; c < 4; c++) acc[mf][nf][c] = 0.f;

    const int K2 = 2 * K0;

    auto ldTile = [&](int kb, float4& a0, float4& a1, float4& b0, float4& b1) {
        const float* A = (kb < K0) ? A1 : A2;
        const float* B = (kb < K0) ? B1 : B2;
        int ko = (kb < K0) ? kb : kb - K0;
        const float* ap = A + (long)(m0 + ar) * K0 + ko + ak;
        a0 = *(const float4*)ap;
        if (MT == 128) a1 = *(const float4*)(ap + 4);
        const float* bp = B + (long)(ko + bk) * N + n0 + bc;
        b0 = *(const float4*)bp;
        b1 = *(const float4*)(bp + 4);
    };

    auto stTile = [&](int kb, int p, float4 a0, float4 a1, float4 b0, float4 b1) {
        int ko = (kb < K0) ? kb : kb - K0;
        if (MT == 128) {
            float av[8] = {a0.x, a0.y, a0.z, a0.w, a1.x, a1.y, a1.z, a1.w};
            if (hasBN && kb >= K0) {
                int c = ko + ak;
#pragma unroll
                for (int j = 0; j < 8; j++)
                    av[j] = fmaxf(fmaf(av[j], s_aa[c + j], s_bb[c + j]), 0.f);
            }
            *(float4*)&As[p][ar][ak] =
                make_float4(tf32r(av[0]), tf32r(av[1]), tf32r(av[2]), tf32r(av[3]));
            *(float4*)&As[p][ar][ak + 4] =
                make_float4(tf32r(av[4]), tf32r(av[5]), tf32r(av[6]), tf32r(av[7]));
        } else {
            float av[4] = {a0.x, a0.y, a0.z, a0.w};
            if (hasBN && kb >= K0) {
                int c = ko + ak;
#pragma unroll
                for (int j = 0; j < 4; j++)
                    av[j] = fmaxf(fmaf(av[j], s_aa[c + j], s_bb[c + j]), 0.f);
            }
            *(float4*)&As[p][ar][ak] =
                make_float4(tf32r(av[0]), tf32r(av[1]), tf32r(av[2]), tf32r(av[3]));
        }
        *(float4*)&Bs[p][bk][bc] =
            make_float4(tf32r(b0.x), tf32r(b0.y), tf32r(b0.z), tf32r(b0.w));
        *(float4*)&Bs[p][bk][bc + 4] =
            make_float4(tf32r(b1.x), tf32r(b1.y), tf32r(b1.z), tf32r(b1.w));
    };

    // prologue
    float4 pa0, pa1, pb0, pb1;
    ldTile(0, pa0, pa1, pb0, pb1);
    __syncthreads();                 // BN coeffs + s_sum init visible
    stTile(0, 0, pa0, pa1, pb0, pb1);
    __syncthreads();

    int p = 0;
    for (int kb = 0; kb < K2; kb += TCBK) {
        int nx = kb + TCBK;
        float4 na0, na1, nb0, nb1;
        if (nx < K2) ldTile(nx, na0, na1, nb0, nb1);

#pragma unroll
        for (int ks = 0; ks < TCBK; ks += 8) {
            unsigned a[MF][4], b[4][2];
#pragma unroll
            for (int mf = 0; mf < MF; mf++) {
                int m = mw + mf * 16 + r;
                a[mf][0] = __float_as_uint(As[p][m][ks + q]);
                a[mf][1] = __float_as_uint(As[p][m + 8][ks + q]);
                a[mf][2] = __float_as_uint(As[p][m][ks + q + 4]);
                a[mf][3] = __float_as_uint(As[p][m + 8][ks + q + 4]);
            }
#pragma unroll
            for (int nf = 0; nf < 4; nf++) {
                int n = nw + nf * 8 + r;
                b[nf][0] = __float_as_uint(Bs[p][ks + q][n]);
                b[nf][1] = __float_as_uint(Bs[p][ks + q + 4][n]);
            }
#pragma unroll
            for (int mf = 0; mf < MF; mf++)
#pragma unroll
                for (int nf = 0; nf < 4; nf++)
                    mma_tf32(acc[mf][nf], a[mf], b[nf]);
        }

        if (nx < K2) stTile(nx, p ^ 1, na0, na1, nb0, nb1);
        __syncthreads();
        p ^= 1;
    }

    float bs0[4], bs1[4];
#pragma unroll
    for (int nf = 0; nf < 4; nf++) {
        int c = n0 + nw + nf * 8 + 2 * q;
        bs0[nf] = bias[c];
        bs1[nf] = bias[c + 1];
    }

    float csum0[4] = {}, csum1[4] = {}, csq0[4] = {}, csq1[4] = {};
#pragma unroll
    for (int mf = 0; mf < MF; mf++) {
        int row0 = m0 + mw + mf * 16 + r;
#pragma unroll
        for (int nf = 0; nf < 4; nf++) {
            int col = n0 + nw + nf * 8 + 2 * q;
            float v0 = acc[mf][nf][0] + bs0[nf];
            float v1 = acc[mf][nf][1] + bs1[nf];
            float v2 = acc[mf][nf][2] + bs0[nf];
            float v3 = acc[mf][nf][3] + bs1[nf];
            *(float2*)(C + (long)row0 * N + col)       = make_float2(v0, v1);
            *(float2*)(C + (long)(row0 + 8) * N + col) = make_float2(v2, v3);
            csum0[nf] += v0 + v2;
            csum1[nf] += v1 + v3;
            csq0[nf]  += v0 * v0 + v2 * v2;
            csq1[nf]  += v1 * v1 + v3 * v3;
        }
    }

    if (stats) {
#pragma unroll
        for (int nf = 0; nf < 4; nf++) {
            int cl = nw + nf * 8 + 2 * q;
            atomicAdd(&s_sum[cl],     csum0[nf]);
            atomicAdd(&s_sum[cl + 1], csum1[nf]);
            atomicAdd(&s_sq[cl],      csq0[nf]);
            atomicAdd(&s_sq[cl + 1],  csq1[nf]);
        }
        __syncthreads();
        if (tid < 128) {
            atomicAdd(&stats[n0 + tid],     s_sum[tid]);
            atomicAdd(&stats[N + n0 + tid], s_sq[tid]);
        }
    }
}

// ---------------- TC 64x64 dual GEMM for the final layer (BN on A2) -----------
// 128 threads (4 warps, 2x2), warp tile 32x32, BK=16, double-buffered.
__global__ __launch_bounds__(128, 4)
void k_gemm_tc64(const float* __restrict__ A1, const float* __restrict__ A2,
                 const float* __restrict__ B1, const float* __restrict__ B2,
                 const float* __restrict__ bias, float* __restrict__ C,
                 int M, int K0, int N,
                 const float* __restrict__ bnst, const float* __restrict__ bng,
                 const float* __restrict__ bnb, float bnInv) {
    __shared__ float As[2][64][20];
    __shared__ float Bs[2][TCBK][72];
    __shared__ float s_aa[256];
    __shared__ float s_bb[256];

    const int tid  = threadIdx.x;
    const int lane = tid & 31;
    const int warp = tid >> 5;
    const int mw = (warp & 1) * 32;
    const int nw = (warp >> 1) * 32;
    const int m0 = blockIdx.x * 64;   // N fits one tile (grid.y == 1)
    const int q = lane & 3, r = lane >> 2;

    const int ar = tid >> 1;          // A row (0..63), 8 floats/thread
    const int ak = (tid & 1) * 8;
    const int bk = tid >> 3;          // B k (0..15), 8 floats/thread
    const int bc = (tid & 7) * 8;

    for (int t = tid; t < 256; t += 128) {
        float m = bnst[t] * bnInv;
        float v = bnst[t + 256] * bnInv - m * m;
        float a = bng[t] * rsqrtf(v + 1e-5f);
        s_aa[t] = a;
        s_bb[t] = bnb[t] - m * a;
    }

    float acc[2][4][4];
#pragma unroll
    for (int mf = 0; mf < 2; mf++)
#pragma unroll
        for (int nf = 0; nf < 4; nf++)
#pragma unroll
            for (int c = 0; c < 4; c++) acc[mf][nf][c] = 0.f;

    const int K2 = 2 * K0;

    auto ldTile = [&](int kb, float4& a0, float4& a1, float4& b0, float4& b1) {
        const float* A = (kb < K0) ? A1 : A2;
        const float* B = (kb < K0) ? B1 : B2;
        int ko = (kb < K0) ? kb : kb - K0;
        const float* ap = A + (long)(m0 + ar) * K0 + ko + ak;
        a0 = *(const float4*)ap;
        a1 = *(const float4*)(ap + 4);
        const float* bp = B + (long)(ko + bk) * N + bc;
        b0 = *(const float4*)bp;
        b1 = *(const float4*)(bp + 4);
    };

    auto stTile = [&](int kb, int p, float4 a0, float4 a1, float4 b0, float4 b1) {
        int ko = (kb < K0) ? kb : kb - K0;
        float av[8] = {a0.x, a0.y, a0.z, a0.w, a1.x, a1.y, a1.z, a1.w};
        if (kb >= K0) {
            int c = ko + ak;
#pragma unroll
            for (int j = 0; j < 8; j++)
                av[j] = fmaxf(fmaf(av[j], s_aa[c + j], s_bb[c + j]), 0.f);
        }
        *(float4*)&As[p][ar][ak] =
            make_float4(tf32r(av[0]), tf32r(av[1]), tf32r(av[2]), tf32r(av[3]));
        *(float4*)&As[p][ar][ak + 4] =
            make_float4(tf32r(av[4]), tf32r(av[5]), tf32r(av[6]), tf32r(av[7]));
        *(float4*)&Bs[p][bk][bc] =
            make_float4(tf32r(b0.x), tf32r(b0.y), tf32r(b0.z), tf32r(b0.w));
        *(float4*)&Bs[p][bk][bc + 4] =
            make_float4(tf32r(b1.x), tf32r(b1.y), tf32r(b1.z), tf32r(b1.w));
    };

    float4 pa0, pa1, pb0, pb1;
    ldTile(0, pa0, pa1, pb0, pb1);
    __syncthreads();                 // s_aa/s_bb visible
    stTile(0, 0, pa0, pa1, pb0, pb1);
    __syncthreads();

    int p = 0;
    for (int kb = 0; kb < K2; kb += TCBK) {
        int nx = kb + TCBK;
        float4 na0, na1, nb0, nb1;
        if (nx < K2) ldTile(nx, na0, na1, nb0, nb1);

#pragma unroll
        for (int ks = 0; ks < TCBK; ks += 8) {
            unsigned a[2][4], b[4][2];
#pragma unroll
            for (int mf = 0; mf < 2; mf++) {
                int m = mw + mf * 16 + r;
                a[mf][0] = __float_as_uint(As[p][m][ks + q]);
                a[mf][1] = __float_as_uint(As[p][m + 8][ks + q]);
                a[mf][2] = __float_as_uint(As[p][m][ks + q + 4]);
                a[mf][3] = __float_as_uint(As[p][m + 8][ks + q + 4]);
            }
#pragma unroll
            for (int nf = 0; nf < 4; nf++) {
                int n = nw + nf * 8 + r;
                b[nf][0] = __float_as_uint(Bs[p][ks + q][n]);
                b[nf][1] = __float_as_uint(Bs[p][ks + q + 4][n]);
            }
#pragma unroll
            for (int mf = 0; mf < 2; mf++)
#pragma unroll
                for (int nf = 0; nf < 4; nf++)
                    mma_tf32(acc[mf][nf], a[mf], b[nf]);
        }

        if (nx < K2) stTile(nx, p ^ 1, na0, na1, nb0, nb1);
        __syncthreads();
        p ^= 1;
    }

    float bs0[4], bs1[4];
#pragma unroll
    for (int nf = 0; nf < 4; nf++) {
        int c = nw + nf * 8 + 2 * q;
        bs0[nf] = bias[c];
        bs1[nf] = bias[c + 1];
    }

#pragma unroll
    for (int mf = 0; mf < 2; mf++) {
        int row0 = m0 + mw + mf * 16 + r;
#pragma unroll
        for (int nf = 0; nf < 4; nf++) {
            int col = nw + nf * 8 + 2 * q;
            *(float2*)(C + (long)row0 * N + col) =
                make_float2(acc[mf][nf][0] + bs0[nf], acc[mf][nf][1] + bs1[nf]);
            *(float2*)(C + (long)(row0 + 8) * N + col) =
                make_float2(acc[mf][nf][2] + bs0[nf], acc[mf][nf][3] + bs1[nf]);
        }
    }
}

// ---------------- launch ------------------------------------------------------
extern "C" void kernel_launch(void* const* d_in, const int* in_sizes, int n_in,
                              void* d_out, int out_size) {
    const float* x      = (const float*)d_in[0];
    const float* Wl0    = (const float*)d_in[1];
    const float* bl0    = (const float*)d_in[2];
    const float* Wr0    = (const float*)d_in[3];
    const float* Wl1    = (const float*)d_in[4];
    const float* bl1    = (const float*)d_in[5];
    const float* Wr1    = (const float*)d_in[6];
    const float* Wl2    = (const float*)d_in[7];
    const float* bl2    = (const float*)d_in[8];
    const float* Wr2    = (const float*)d_in[9];
    const float* gamma0 = (const float*)d_in[10];
    const float* beta0  = (const float*)d_in[11];
    const float* gamma1 = (const float*)d_in[12];
    const float* beta1  = (const float*)d_in[13];
    const int* src0 = (const int*)d_in[14];
    const int* dst0 = (const int*)d_in[15];
    const int* src1 = (const int*)d_in[16];
    const int* dst1 = (const int*)d_in[17];
    const int* src2 = (const int*)d_in[18];
    const int* dst2 = (const int*)d_in[19];
    float* out = (float*)d_out;

    float *agg, *h1, *h2;
    int *zero, *off0, *off1, *off2, *e0, *e1, *e2;
    cudaGetSymbolAddress((void**)&agg, g_agg);
    cudaGetSymbolAddress((void**)&h1, g_h1);
    cudaGetSymbolAddress((void**)&h2, g_h2);
    cudaGetSymbolAddress((void**)&zero, g_zero);
    cudaGetSymbolAddress((void**)&off0, g_off0);
    cudaGetSymbolAddress((void**)&off1, g_off1);
    cudaGetSymbolAddress((void**)&off2, g_off2);
    cudaGetSymbolAddress((void**)&e0, g_esrc0);
    cudaGetSymbolAddress((void**)&e1, g_esrc1);
    cudaGetSymbolAddress((void**)&e2, g_esrc2);

    int* deg = zero;
    int* cur = zero + NTOT;
    float* stats0 = (float*)(zero + 2 * NTOT);
    float* stats1 = stats0 + 2 * DH;

    // --- combined CSR build + zeroing ---
    cudaMemsetAsync(zero, 0, sizeof(int) * (2 * NTOT + 4 * DH), 0);
    k_hist_all<<<(NETOT + 255) / 256, 256>>>(dst0, dst1, dst2, deg);
    k_scan3<<<3, 1024>>>(deg, off0, off1, off2);
    k_bucket_all<<<(NETOT + 255) / 256, 256>>>(src0, dst0, src1, dst1, src2, dst2,
                                               off0, off1, off2, cur, e0, e1, e2);

    // --- layer 0: IN=128 -> H=256, M = 25600 ---
    k_gather<DIN, false><<<NDST0 * 32 / 256, 256>>>(x, e0, off0, agg, NDST0,
                                                    nullptr, nullptr, nullptr, 0.f);
    {
        dim3 g(NDST0 / 128, DH / 128);
        k_gemm_tc<128><<<g, 256>>>(agg, x, Wl0, Wr0, bl0, h1, NDST0, DIN, DH, stats0,
                                   nullptr, nullptr, nullptr, 0.f);
    }

    // --- layer 1: H=256 -> H=256, M = 5120 (BN0 fused; MT=64 for SM fill) ---
    k_gather<DH, true><<<NDST1 * 32 / 256, 256>>>(h1, e1, off1, agg, NDST1,
                                                  stats0, gamma0, beta0, 1.0f / NDST0);
    {
        dim3 g(NDST1 / 64, DH / 128);
        k_gemm_tc<64><<<g, 256>>>(agg, h1, Wl1, Wr1, bl1, h2, NDST1, DH, DH, stats1,
                                  stats0, gamma0, beta0, 1.0f / NDST0);
    }

    // --- layer 2: H=256 -> OUT=64, M = 1024 (BN1 fused; TC) ---
    k_gather<DH, true><<<NDST2 * 32 / 256, 256>>>(h2, e2, off2, agg, NDST2,
                                                  stats1, gamma1, beta1, 1.0f / NDST1);
    {
        dim3 g(NDST2 / 64, 1);
        k_gemm_tc64<<<g, 128>>>(agg, h2, Wl2, Wr2, bl2, out, NDST2, DH, DOUT,
                                stats1, gamma1, beta1, 1.0f / NDST1);
    }
}